// round 1
// baseline (speedup 1.0000x reference)
#include <cuda_runtime.h>
#include <math.h>

#define L_SEQ   1024
#define INLEN   512
#define DMODEL  1024
#define NLAYERS 4
#define DINNER  2048
#define DSTATE  16
#define DTRANK  64
#define XDBL_W  96   // DT_RANK + 2*D_STATE

// ---------------- scratch (device globals: no allocations allowed) ----------
__device__ float g_res  [L_SEQ * DMODEL];
__device__ float g_hn   [L_SEQ * DMODEL];
__device__ float g_h    [L_SEQ * DMODEL];
__device__ float g_xz   [L_SEQ * 2 * DINNER];
__device__ float g_xconv[L_SEQ * DINNER];
__device__ float g_xdbl [L_SEQ * XDBL_W];
__device__ float g_delta[L_SEQ * DINNER];
__device__ float g_y    [L_SEQ * DINNER];

// ---------------- generic NT SGEMM: C[m,n] = sum_k A[m,k]*B[n,k] -------------
// mode 0: plain store
// mode 1: softplus(acc + bias[n]) store   (dt_proj epilogue)
// mode 2: atomicAdd (split-K via gridDim.z; C pre-zeroed)
template<int BM, int BN, int BK, int TM, int TN>
__global__ void __launch_bounds__((BM/TM)*(BN/TN))
sgemm_nt(const float* __restrict__ A, int lda,
         const float* __restrict__ B, int ldb,
         float* __restrict__ C, int ldc,
         int M, int N, int K,
         const float* __restrict__ bias, int mode)
{
    constexpr int THREADS = (BM/TM)*(BN/TN);
    __shared__ float As[BK][BM];
    __shared__ float Bs[BK][BN];

    const int tid = threadIdx.x;
    const int tx  = tid % (BN/TN);
    const int ty  = tid / (BN/TN);
    const int m0  = blockIdx.y * BM;
    const int n0  = blockIdx.x * BN;

    int kBeg = 0, kEnd = K;
    if (gridDim.z > 1) {
        int kc = K / gridDim.z;
        kBeg = blockIdx.z * kc;
        kEnd = kBeg + kc;
    }

    float acc[TM][TN];
#pragma unroll
    for (int i = 0; i < TM; i++)
#pragma unroll
        for (int j = 0; j < TN; j++) acc[i][j] = 0.f;

    for (int k0 = kBeg; k0 < kEnd; k0 += BK) {
        // load A tile (BM x BK), store transposed As[k][m]
        for (int v = tid; v < (BM*BK)/4; v += THREADS) {
            int lin = v * 4;
            int r = lin / BK, c = lin % BK;
            int gm = m0 + r;
            float4 t = make_float4(0.f, 0.f, 0.f, 0.f);
            if (gm < M)
                t = *reinterpret_cast<const float4*>(A + (size_t)gm * lda + k0 + c);
            As[c+0][r] = t.x; As[c+1][r] = t.y; As[c+2][r] = t.z; As[c+3][r] = t.w;
        }
        // load B tile (BN x BK), store transposed Bs[k][n]
        for (int v = tid; v < (BN*BK)/4; v += THREADS) {
            int lin = v * 4;
            int r = lin / BK, c = lin % BK;
            int gn = n0 + r;
            float4 t = make_float4(0.f, 0.f, 0.f, 0.f);
            if (gn < N)
                t = *reinterpret_cast<const float4*>(B + (size_t)gn * ldb + k0 + c);
            Bs[c+0][r] = t.x; Bs[c+1][r] = t.y; Bs[c+2][r] = t.z; Bs[c+3][r] = t.w;
        }
        __syncthreads();

#pragma unroll
        for (int k = 0; k < BK; k++) {
            float a[TM], b[TN];
#pragma unroll
            for (int i = 0; i < TM; i++) a[i] = As[k][ty*TM + i];
#pragma unroll
            for (int j = 0; j < TN; j++) b[j] = Bs[k][tx*TN + j];
#pragma unroll
            for (int i = 0; i < TM; i++)
#pragma unroll
                for (int j = 0; j < TN; j++)
                    acc[i][j] = fmaf(a[i], b[j], acc[i][j]);
        }
        __syncthreads();
    }

#pragma unroll
    for (int i = 0; i < TM; i++) {
        int gm = m0 + ty*TM + i;
        if (gm >= M) continue;
#pragma unroll
        for (int j = 0; j < TN; j++) {
            int gn = n0 + tx*TN + j;
            if (gn >= N) continue;
            float v = acc[i][j];
            if (mode == 1) {
                v += bias[gn];
                v = (v > 20.f) ? v : log1pf(expf(v));   // softplus
            }
            if (mode == 2) atomicAdd(&C[(size_t)gm * ldc + gn], v);
            else           C[(size_t)gm * ldc + gn] = v;
        }
    }
}

// ---------------- fused residual-add + LayerNorm -----------------------------
// res = (first ? hin : res + hin);  hn = LN(res) * w + b
__global__ void resln_kernel(const float* __restrict__ hin,
                             float* __restrict__ res,
                             float* __restrict__ hn,
                             const float* __restrict__ w,
                             const float* __restrict__ b,
                             int first)
{
    const int l   = blockIdx.x;      // 1024 rows
    const int tid = threadIdx.x;     // 256 threads
    float v[4];
    float s = 0.f, sq = 0.f;
#pragma unroll
    for (int i = 0; i < 4; i++) {
        int c = tid + i * 256;
        float x = hin[l * DMODEL + c];
        if (!first) x += res[l * DMODEL + c];
        res[l * DMODEL + c] = x;
        v[i] = x;
        s  += x;
        sq += x * x;
    }
    // block reduce
    __shared__ float shs[8], shq[8];
    const int lane = tid & 31, warp = tid >> 5;
#pragma unroll
    for (int o = 16; o > 0; o >>= 1) {
        s  += __shfl_xor_sync(0xffffffffu, s,  o);
        sq += __shfl_xor_sync(0xffffffffu, sq, o);
    }
    if (lane == 0) { shs[warp] = s; shq[warp] = sq; }
    __syncthreads();
    s = 0.f; sq = 0.f;
#pragma unroll
    for (int i = 0; i < 8; i++) { s += shs[i]; sq += shq[i]; }

    const float inv = 1.f / (float)DMODEL;
    const float mu  = s * inv;
    const float var = sq * inv - mu * mu;
    const float rstd = rsqrtf(var + 1e-5f);
#pragma unroll
    for (int i = 0; i < 4; i++) {
        int c = tid + i * 256;
        hn[l * DMODEL + c] = (v[i] - mu) * rstd * w[c] + b[c];
    }
}

// ---------------- causal depthwise conv (D_CONV=4) + SiLU; zero x_dbl --------
__global__ void conv_silu_kernel(const float* __restrict__ xz,
                                 const float* __restrict__ cw,
                                 const float* __restrict__ cb,
                                 float* __restrict__ xconv,
                                 float* __restrict__ xdbl)
{
    const int idx = blockIdx.x * blockDim.x + threadIdx.x;
    if (idx >= L_SEQ * DINNER) return;
    const int l = idx >> 11;           // /2048
    const int d = idx & (DINNER - 1);  // %2048

    float acc = cb[d];
    const float w0 = cw[d*4+0], w1 = cw[d*4+1], w2 = cw[d*4+2], w3 = cw[d*4+3];
    if (l >= 3) acc = fmaf(w0, xz[(size_t)(l-3) * (2*DINNER) + d], acc);
    if (l >= 2) acc = fmaf(w1, xz[(size_t)(l-2) * (2*DINNER) + d], acc);
    if (l >= 1) acc = fmaf(w2, xz[(size_t)(l-1) * (2*DINNER) + d], acc);
    acc = fmaf(w3, xz[(size_t)l * (2*DINNER) + d], acc);

    acc = acc / (1.f + expf(-acc));    // SiLU
    xconv[idx] = acc;

    if (idx < L_SEQ * XDBL_W) xdbl[idx] = 0.f;  // pre-zero for split-K atomics
}

// ---------------- selective scan + D-skip + SiLU(z) gate ---------------------
// One warp handles 2 channels (16 state-lanes each); 16 channels / block.
__global__ void scan_kernel(const float* __restrict__ delta,
                            const float* __restrict__ xdbl,
                            const float* __restrict__ xconv,
                            const float* __restrict__ xz,
                            const float* __restrict__ A_log,
                            const float* __restrict__ Dvec,
                            float* __restrict__ y)
{
    const int warp = threadIdx.x >> 5;
    const int lane = threadIdx.x & 31;
    const int grp  = lane >> 4;          // 0 or 1 within warp
    const int s    = lane & 15;          // state index
    const int d    = blockIdx.x * 16 + warp * 2 + grp;

    const float a2 = -expf(A_log[d * DSTATE + s]) * 1.4426950408889634f; // A*log2(e)
    const float Dd = Dvec[d];

    float h = 0.f;
    for (int t = 0; t < L_SEQ; t++) {
        const float dl = delta[(size_t)t * DINNER + d];
        const float xv = xconv[(size_t)t * DINNER + d];
        const float Bs = xdbl[t * XDBL_W + DTRANK + s];
        const float Cs = xdbl[t * XDBL_W + DTRANK + DSTATE + s];

        const float dA = exp2f(dl * a2);
        h = fmaf(dA, h, dl * xv * Bs);

        float acc = h * Cs;
        acc += __shfl_xor_sync(0xffffffffu, acc, 1);
        acc += __shfl_xor_sync(0xffffffffu, acc, 2);
        acc += __shfl_xor_sync(0xffffffffu, acc, 4);
        acc += __shfl_xor_sync(0xffffffffu, acc, 8);

        if (s == 0) {
            const float zv = xz[(size_t)t * (2*DINNER) + DINNER + d];
            float yv = acc + xv * Dd;
            yv *= zv / (1.f + expf(-zv));   // * silu(z)
            y[(size_t)t * DINNER + d] = yv;
        }
    }
}

// ---------------- host orchestration ----------------------------------------
extern "C" void kernel_launch(void* const* d_in, const int* in_sizes, int n_in,
                              void* d_out, int out_size)
{
    const float* input   = (const float*)d_in[0];
    // d_in[1] = inference_parameters (unused)
    const float* input_w = (const float*)d_in[2];
    const float* norm_w  = (const float*)d_in[3];
    const float* norm_b  = (const float*)d_in[4];
    const float* ipw     = (const float*)d_in[5];
    const float* cw      = (const float*)d_in[6];
    const float* cb      = (const float*)d_in[7];
    const float* xpw     = (const float*)d_in[8];
    const float* dtw     = (const float*)d_in[9];
    const float* dtb     = (const float*)d_in[10];
    const float* A_log   = (const float*)d_in[11];
    const float* ssm_D   = (const float*)d_in[12];
    const float* opw     = (const float*)d_in[13];

    float *res, *hn, *h, *xz, *xconv, *xdbl, *delta, *y;
    cudaGetSymbolAddress((void**)&res,   g_res);
    cudaGetSymbolAddress((void**)&hn,    g_hn);
    cudaGetSymbolAddress((void**)&h,     g_h);
    cudaGetSymbolAddress((void**)&xz,    g_xz);
    cudaGetSymbolAddress((void**)&xconv, g_xconv);
    cudaGetSymbolAddress((void**)&xdbl,  g_xdbl);
    cudaGetSymbolAddress((void**)&delta, g_delta);
    cudaGetSymbolAddress((void**)&y,     g_y);

    // h = input @ input_w^T   [1024,512] x [1024,512]^T -> [1024,1024]
    sgemm_nt<128,64,8,8,4><<<dim3(DMODEL/64, L_SEQ/128), 256>>>(
        input, INLEN, input_w, INLEN, h, DMODEL,
        L_SEQ, DMODEL, INLEN, nullptr, 0);

    for (int i = 0; i < NLAYERS; i++) {
        // residual + LN
        resln_kernel<<<L_SEQ, 256>>>(h, res, hn,
                                     norm_w + i*DMODEL, norm_b + i*DMODEL, i == 0);

        // xz = hn @ in_proj_w^T   [1024,1024] x [4096,1024]^T
        sgemm_nt<128,128,8,8,8><<<dim3((2*DINNER)/128, L_SEQ/128), 256>>>(
            hn, DMODEL, ipw + (size_t)i*2*DINNER*DMODEL, DMODEL, xz, 2*DINNER,
            L_SEQ, 2*DINNER, DMODEL, nullptr, 0);

        // conv + silu (+ zero x_dbl for split-K)
        conv_silu_kernel<<<(L_SEQ*DINNER)/256, 256>>>(
            xz, cw + (size_t)i*DINNER*4, cb + i*DINNER, xconv, xdbl);

        // x_dbl = xconv @ x_proj_w^T   [1024,2048] x [96,2048]^T  (split-K=4, atomic)
        sgemm_nt<16,128,8,1,8><<<dim3(1, L_SEQ/16, 4), 256>>>(
            xconv, DINNER, xpw + (size_t)i*XDBL_W*DINNER, DINNER, xdbl, XDBL_W,
            L_SEQ, XDBL_W, DINNER, nullptr, 2);

        // delta = softplus(x_dbl[:, :64] @ dt_proj_w^T + dt_bias)
        sgemm_nt<128,128,8,8,8><<<dim3(DINNER/128, L_SEQ/128), 256>>>(
            xdbl, XDBL_W, dtw + (size_t)i*DINNER*DTRANK, DTRANK, delta, DINNER,
            L_SEQ, DINNER, DTRANK, dtb + i*DINNER, 1);

        // selective scan + epilogue
        scan_kernel<<<DINNER/16, 256>>>(delta, xdbl, xconv, xz,
                                        A_log + (size_t)i*DINNER*DSTATE,
                                        ssm_D + i*DINNER, y);

        // h(next) = y @ out_proj_w^T   [1024,2048] x [1024,2048]^T
        float* outp = (i == NLAYERS-1) ? (float*)d_out : h;
        sgemm_nt<128,64,8,8,4><<<dim3(DMODEL/64, L_SEQ/128), 256>>>(
            y, DINNER, opw + (size_t)i*DMODEL*DINNER, DINNER, outp, DMODEL,
            L_SEQ, DMODEL, DINNER, nullptr, 0);
    }
}

// round 2
// speedup vs baseline: 1.0929x; 1.0929x over previous
#include <cuda_runtime.h>
#include <math.h>

#define L_SEQ   1024
#define INLEN   512
#define DMODEL  1024
#define NLAYERS 4
#define DINNER  2048
#define DSTATE  16
#define DTRANK  64
#define XDBL_W  96   // DT_RANK + 2*D_STATE

// ---------------- scratch (device globals: no allocations allowed) ----------
__device__ float g_res  [L_SEQ * DMODEL];
__device__ float g_hn   [L_SEQ * DMODEL];
__device__ float g_h    [L_SEQ * DMODEL];
__device__ float g_xz   [L_SEQ * 2 * DINNER];
__device__ float g_xconv[L_SEQ * DINNER];
__device__ float g_xdbl [L_SEQ * XDBL_W];
__device__ float g_delta[L_SEQ * DINNER];
__device__ float g_y    [L_SEQ * DINNER];

// =============================================================================
// Double-buffered NT SGEMM: C[m,n] = sum_k A[m,k]*B[n,k]
// Requirements (all satisfied by our shapes): M%BM==0, N%BN==0, K%BK==0,
// lda/ldb/ldc multiples of 4.
// mode 0: plain store;  mode 1: softplus(acc + bias[n]) (dt_proj epilogue)
// =============================================================================
template<int BM, int BN, int BK, int TM, int TN>
__global__ void __launch_bounds__((BM/TM)*(BN/TN))
sgemm_db(const float* __restrict__ A, int lda,
         const float* __restrict__ B, int ldb,
         float* __restrict__ C, int ldc,
         int K, const float* __restrict__ bias, int mode)
{
    constexpr int THREADS = (BM/TM)*(BN/TN);
    constexpr int A_V4 = (BM*BK/4)/THREADS;
    constexpr int B_V4 = (BN*BK/4)/THREADS;
    static_assert(A_V4 >= 1 && B_V4 >= 1, "tile/thread mismatch");

    __shared__ float As[2][BK][BM];
    __shared__ float Bs[2][BK][BN];

    const int tid = threadIdx.x;
    const int tx  = tid % (BN/TN);
    const int ty  = tid / (BN/TN);
    const int m0  = blockIdx.y * BM;
    const int n0  = blockIdx.x * BN;

    const float* Ab = A + (size_t)m0 * lda;
    const float* Bb = B + (size_t)n0 * ldb;

    float4 ra[A_V4], rb[B_V4];
    float acc[TM][TN];
#pragma unroll
    for (int i = 0; i < TM; i++)
#pragma unroll
        for (int j = 0; j < TN; j++) acc[i][j] = 0.f;

    // ---- helpers ----
    auto ldgA = [&](int k0) {
#pragma unroll
        for (int i = 0; i < A_V4; i++) {
            int lin = (tid + i * THREADS) * 4;
            int r = lin / BK, c = lin % BK;
            ra[i] = *reinterpret_cast<const float4*>(Ab + (size_t)r * lda + k0 + c);
        }
    };
    auto ldgB = [&](int k0) {
#pragma unroll
        for (int i = 0; i < B_V4; i++) {
            int lin = (tid + i * THREADS) * 4;
            int r = lin / BK, c = lin % BK;
            rb[i] = *reinterpret_cast<const float4*>(Bb + (size_t)r * ldb + k0 + c);
        }
    };
    auto sts = [&](int buf) {
#pragma unroll
        for (int i = 0; i < A_V4; i++) {
            int lin = (tid + i * THREADS) * 4;
            int r = lin / BK, c = lin % BK;
            As[buf][c+0][r] = ra[i].x; As[buf][c+1][r] = ra[i].y;
            As[buf][c+2][r] = ra[i].z; As[buf][c+3][r] = ra[i].w;
        }
#pragma unroll
        for (int i = 0; i < B_V4; i++) {
            int lin = (tid + i * THREADS) * 4;
            int r = lin / BK, c = lin % BK;
            Bs[buf][c+0][r] = rb[i].x; Bs[buf][c+1][r] = rb[i].y;
            Bs[buf][c+2][r] = rb[i].z; Bs[buf][c+3][r] = rb[i].w;
        }
    };
    auto compute = [&](int buf) {
#pragma unroll
        for (int k = 0; k < BK; k++) {
            float a[TM], b[TN];
#pragma unroll
            for (int i = 0; i < TM; i += 4) {
                float4 t = *reinterpret_cast<const float4*>(&As[buf][k][ty*TM + i]);
                a[i+0] = t.x; a[i+1] = t.y; a[i+2] = t.z; a[i+3] = t.w;
            }
#pragma unroll
            for (int j = 0; j < TN; j += 4) {
                float4 t = *reinterpret_cast<const float4*>(&Bs[buf][k][tx*TN + j]);
                b[j+0] = t.x; b[j+1] = t.y; b[j+2] = t.z; b[j+3] = t.w;
            }
#pragma unroll
            for (int i = 0; i < TM; i++)
#pragma unroll
                for (int j = 0; j < TN; j++)
                    acc[i][j] = fmaf(a[i], b[j], acc[i][j]);
        }
    };

    // ---- prologue ----
    ldgA(0); ldgB(0);
    sts(0);
    __syncthreads();

    int buf = 0;
    for (int k0 = BK; k0 < K; k0 += BK) {
        ldgA(k0); ldgB(k0);      // prefetch next tile into registers
        compute(buf);            // compute on current smem buffer
        sts(buf ^ 1);            // stage next tile
        __syncthreads();
        buf ^= 1;
    }
    compute(buf);

    // ---- epilogue (float4 stores) ----
#pragma unroll
    for (int i = 0; i < TM; i++) {
        int gm = m0 + ty*TM + i;
        float* crow = C + (size_t)gm * ldc + n0 + tx*TN;
#pragma unroll
        for (int j = 0; j < TN; j += 4) {
            float4 v;
            v.x = acc[i][j+0]; v.y = acc[i][j+1];
            v.z = acc[i][j+2]; v.w = acc[i][j+3];
            if (mode == 1) {
                int gn = n0 + tx*TN + j;
                v.x += bias[gn+0]; v.y += bias[gn+1];
                v.z += bias[gn+2]; v.w += bias[gn+3];
                v.x = (v.x > 20.f) ? v.x : log1pf(expf(v.x));
                v.y = (v.y > 20.f) ? v.y : log1pf(expf(v.y));
                v.z = (v.z > 20.f) ? v.z : log1pf(expf(v.z));
                v.w = (v.w > 20.f) ? v.w : log1pf(expf(v.w));
            }
            *reinterpret_cast<float4*>(crow + j) = v;
        }
    }
}

// ---------------- small split-K SGEMM (x_proj only, N=96) -------------------
// mode 2: atomicAdd (split-K via gridDim.z; C pre-zeroed)
template<int BM, int BN, int BK, int TM, int TN>
__global__ void __launch_bounds__((BM/TM)*(BN/TN))
sgemm_nt(const float* __restrict__ A, int lda,
         const float* __restrict__ B, int ldb,
         float* __restrict__ C, int ldc,
         int M, int N, int K)
{
    constexpr int THREADS = (BM/TM)*(BN/TN);
    __shared__ float As[BK][BM];
    __shared__ float Bs[BK][BN];

    const int tid = threadIdx.x;
    const int tx  = tid % (BN/TN);
    const int ty  = tid / (BN/TN);
    const int m0  = blockIdx.y * BM;
    const int n0  = blockIdx.x * BN;

    int kc = K / gridDim.z;
    int kBeg = blockIdx.z * kc;
    int kEnd = kBeg + kc;

    float acc[TM][TN];
#pragma unroll
    for (int i = 0; i < TM; i++)
#pragma unroll
        for (int j = 0; j < TN; j++) acc[i][j] = 0.f;

    for (int k0 = kBeg; k0 < kEnd; k0 += BK) {
        for (int v = tid; v < (BM*BK)/4; v += THREADS) {
            int lin = v * 4;
            int r = lin / BK, c = lin % BK;
            int gm = m0 + r;
            float4 t = make_float4(0.f, 0.f, 0.f, 0.f);
            if (gm < M)
                t = *reinterpret_cast<const float4*>(A + (size_t)gm * lda + k0 + c);
            As[c+0][r] = t.x; As[c+1][r] = t.y; As[c+2][r] = t.z; As[c+3][r] = t.w;
        }
        for (int v = tid; v < (BN*BK)/4; v += THREADS) {
            int lin = v * 4;
            int r = lin / BK, c = lin % BK;
            int gn = n0 + r;
            float4 t = make_float4(0.f, 0.f, 0.f, 0.f);
            if (gn < N)
                t = *reinterpret_cast<const float4*>(B + (size_t)gn * ldb + k0 + c);
            Bs[c+0][r] = t.x; Bs[c+1][r] = t.y; Bs[c+2][r] = t.z; Bs[c+3][r] = t.w;
        }
        __syncthreads();
#pragma unroll
        for (int k = 0; k < BK; k++) {
            float a[TM], b[TN];
#pragma unroll
            for (int i = 0; i < TM; i++) a[i] = As[k][ty*TM + i];
#pragma unroll
            for (int j = 0; j < TN; j++) b[j] = Bs[k][tx*TN + j];
#pragma unroll
            for (int i = 0; i < TM; i++)
#pragma unroll
                for (int j = 0; j < TN; j++)
                    acc[i][j] = fmaf(a[i], b[j], acc[i][j]);
        }
        __syncthreads();
    }

#pragma unroll
    for (int i = 0; i < TM; i++) {
        int gm = m0 + ty*TM + i;
        if (gm >= M) continue;
#pragma unroll
        for (int j = 0; j < TN; j++) {
            int gn = n0 + tx*TN + j;
            if (gn >= N) continue;
            atomicAdd(&C[(size_t)gm * ldc + gn], acc[i][j]);
        }
    }
}

// ---------------- fused residual-add + LayerNorm -----------------------------
__global__ void resln_kernel(const float* __restrict__ hin,
                             float* __restrict__ res,
                             float* __restrict__ hn,
                             const float* __restrict__ w,
                             const float* __restrict__ b,
                             int first)
{
    const int l   = blockIdx.x;
    const int tid = threadIdx.x;
    float v[4];
    float s = 0.f, sq = 0.f;
#pragma unroll
    for (int i = 0; i < 4; i++) {
        int c = tid + i * 256;
        float x = hin[l * DMODEL + c];
        if (!first) x += res[l * DMODEL + c];
        res[l * DMODEL + c] = x;
        v[i] = x;
        s  += x;
        sq += x * x;
    }
    __shared__ float shs[8], shq[8];
    const int lane = tid & 31, warp = tid >> 5;
#pragma unroll
    for (int o = 16; o > 0; o >>= 1) {
        s  += __shfl_xor_sync(0xffffffffu, s,  o);
        sq += __shfl_xor_sync(0xffffffffu, sq, o);
    }
    if (lane == 0) { shs[warp] = s; shq[warp] = sq; }
    __syncthreads();
    s = 0.f; sq = 0.f;
#pragma unroll
    for (int i = 0; i < 8; i++) { s += shs[i]; sq += shq[i]; }

    const float inv = 1.f / (float)DMODEL;
    const float mu  = s * inv;
    const float var = sq * inv - mu * mu;
    const float rstd = rsqrtf(var + 1e-5f);
#pragma unroll
    for (int i = 0; i < 4; i++) {
        int c = tid + i * 256;
        hn[l * DMODEL + c] = (v[i] - mu) * rstd * w[c] + b[c];
    }
}

// ---------------- causal depthwise conv (D_CONV=4) + SiLU; zero x_dbl --------
__global__ void conv_silu_kernel(const float* __restrict__ xz,
                                 const float* __restrict__ cw,
                                 const float* __restrict__ cb,
                                 float* __restrict__ xconv,
                                 float* __restrict__ xdbl)
{
    const int idx = blockIdx.x * blockDim.x + threadIdx.x;
    if (idx >= L_SEQ * DINNER) return;
    const int l = idx >> 11;
    const int d = idx & (DINNER - 1);

    float acc = cb[d];
    const float w0 = cw[d*4+0], w1 = cw[d*4+1], w2 = cw[d*4+2], w3 = cw[d*4+3];
    if (l >= 3) acc = fmaf(w0, xz[(size_t)(l-3) * (2*DINNER) + d], acc);
    if (l >= 2) acc = fmaf(w1, xz[(size_t)(l-2) * (2*DINNER) + d], acc);
    if (l >= 1) acc = fmaf(w2, xz[(size_t)(l-1) * (2*DINNER) + d], acc);
    acc = fmaf(w3, xz[(size_t)l * (2*DINNER) + d], acc);

    acc = acc / (1.f + expf(-acc));
    xconv[idx] = acc;

    if (idx < L_SEQ * XDBL_W) xdbl[idx] = 0.f;
}

// ---------------- selective scan + D-skip + SiLU(z) gate ---------------------
__global__ void scan_kernel(const float* __restrict__ delta,
                            const float* __restrict__ xdbl,
                            const float* __restrict__ xconv,
                            const float* __restrict__ xz,
                            const float* __restrict__ A_log,
                            const float* __restrict__ Dvec,
                            float* __restrict__ y)
{
    const int warp = threadIdx.x >> 5;
    const int lane = threadIdx.x & 31;
    const int grp  = lane >> 4;
    const int s    = lane & 15;
    const int d    = blockIdx.x * 16 + warp * 2 + grp;

    const float a2 = -expf(A_log[d * DSTATE + s]) * 1.4426950408889634f;
    const float Dd = Dvec[d];

    float h = 0.f;
    for (int t = 0; t < L_SEQ; t++) {
        const float dl = delta[(size_t)t * DINNER + d];
        const float xv = xconv[(size_t)t * DINNER + d];
        const float Bs = xdbl[t * XDBL_W + DTRANK + s];
        const float Cs = xdbl[t * XDBL_W + DTRANK + DSTATE + s];

        const float dA = exp2f(dl * a2);
        h = fmaf(dA, h, dl * xv * Bs);

        float acc = h * Cs;
        acc += __shfl_xor_sync(0xffffffffu, acc, 1);
        acc += __shfl_xor_sync(0xffffffffu, acc, 2);
        acc += __shfl_xor_sync(0xffffffffu, acc, 4);
        acc += __shfl_xor_sync(0xffffffffu, acc, 8);

        if (s == 0) {
            const float zv = xz[(size_t)t * (2*DINNER) + DINNER + d];
            float yv = acc + xv * Dd;
            yv *= zv / (1.f + expf(-zv));
            y[(size_t)t * DINNER + d] = yv;
        }
    }
}

// ---------------- host orchestration ----------------------------------------
extern "C" void kernel_launch(void* const* d_in, const int* in_sizes, int n_in,
                              void* d_out, int out_size)
{
    const float* input   = (const float*)d_in[0];
    const float* input_w = (const float*)d_in[2];
    const float* norm_w  = (const float*)d_in[3];
    const float* norm_b  = (const float*)d_in[4];
    const float* ipw     = (const float*)d_in[5];
    const float* cw      = (const float*)d_in[6];
    const float* cb      = (const float*)d_in[7];
    const float* xpw     = (const float*)d_in[8];
    const float* dtw     = (const float*)d_in[9];
    const float* dtb     = (const float*)d_in[10];
    const float* A_log   = (const float*)d_in[11];
    const float* ssm_D   = (const float*)d_in[12];
    const float* opw     = (const float*)d_in[13];

    float *res, *hn, *h, *xz, *xconv, *xdbl, *delta, *y;
    cudaGetSymbolAddress((void**)&res,   g_res);
    cudaGetSymbolAddress((void**)&hn,    g_hn);
    cudaGetSymbolAddress((void**)&h,     g_h);
    cudaGetSymbolAddress((void**)&xz,    g_xz);
    cudaGetSymbolAddress((void**)&xconv, g_xconv);
    cudaGetSymbolAddress((void**)&xdbl,  g_xdbl);
    cudaGetSymbolAddress((void**)&delta, g_delta);
    cudaGetSymbolAddress((void**)&y,     g_y);

    // h = input @ input_w^T   [1024,512] x [1024,512]^T -> [1024,1024]
    // 64x128 tiles -> 8 x 16 = 128 CTAs, 256 thr (8 warps/SM)
    sgemm_db<64,128,16,4,8><<<dim3(DMODEL/128, L_SEQ/64), 256>>>(
        input, INLEN, input_w, INLEN, h, DMODEL, INLEN, nullptr, 0);

    for (int i = 0; i < NLAYERS; i++) {
        resln_kernel<<<L_SEQ, 256>>>(h, res, hn,
                                     norm_w + i*DMODEL, norm_b + i*DMODEL, i == 0);

        // xz = hn @ in_proj_w^T  [1024,1024]x[4096,1024]^T -> 256 CTAs
        sgemm_db<128,128,16,8,8><<<dim3((2*DINNER)/128, L_SEQ/128), 256>>>(
            hn, DMODEL, ipw + (size_t)i*2*DINNER*DMODEL, DMODEL, xz, 2*DINNER,
            DMODEL, nullptr, 0);

        conv_silu_kernel<<<(L_SEQ*DINNER)/256, 256>>>(
            xz, cw + (size_t)i*DINNER*4, cb + i*DINNER, xconv, xdbl);

        // x_dbl = xconv @ x_proj_w^T  (N=96, split-K=4, atomic)
        sgemm_nt<16,128,8,1,8><<<dim3(1, L_SEQ/16, 4), 256>>>(
            xconv, DINNER, xpw + (size_t)i*XDBL_W*DINNER, DINNER, xdbl, XDBL_W,
            L_SEQ, XDBL_W, DINNER);

        // delta = softplus(x_dbl[:, :64] @ dt_proj_w^T + dt_bias)  -> 128 CTAs
        sgemm_db<128,128,16,8,8><<<dim3(DINNER/128, L_SEQ/128), 256>>>(
            xdbl, XDBL_W, dtw + (size_t)i*DINNER*DTRANK, DTRANK, delta, DINNER,
            DTRANK, dtb + i*DINNER, 1);

        scan_kernel<<<DINNER/16, 256>>>(delta, xdbl, xconv, xz,
                                        A_log + (size_t)i*DINNER*DSTATE,
                                        ssm_D + i*DINNER, y);

        // h(next) = y @ out_proj_w^T  [1024,1024,K=2048] 64x128 -> 128 CTAs
        float* outp = (i == NLAYERS-1) ? (float*)d_out : h;
        sgemm_db<64,128,16,4,8><<<dim3(DMODEL/128, L_SEQ/64), 256>>>(
            y, DINNER, opw + (size_t)i*DMODEL*DINNER, DINNER, outp, DMODEL,
            DINNER, nullptr, 0);
    }
}

// round 4
// speedup vs baseline: 1.3885x; 1.2704x over previous
#include <cuda_runtime.h>
#include <cuda_bf16.h>
#include <math.h>
#include <stdint.h>

#define L_SEQ   1024
#define INLEN   512
#define DMODEL  1024
#define NLAYERS 4
#define DINNER  2048
#define DSTATE  16
#define DTRANK  64
#define XDBL_W  96   // DT_RANK + 2*D_STATE

// ---------------- scratch (device globals: no allocations allowed) ----------
__device__ float g_res  [L_SEQ * DMODEL];
__device__ float g_hn   [L_SEQ * DMODEL];
__device__ float g_h    [L_SEQ * DMODEL];
__device__ float g_xz   [L_SEQ * 2 * DINNER];
__device__ float g_xconv[L_SEQ * DINNER];
__device__ float g_xdbl [L_SEQ * XDBL_W];
__device__ float g_delta[L_SEQ * DINNER];
__device__ float g_y    [L_SEQ * DINNER];

#define SMEM_SWIZZLE_128B(off) ((off) ^ (((off) >> 3) & 0x70))

__device__ __forceinline__ uint32_t pack_bf16x2(float lo, float hi) {
    __nv_bfloat16 a = __float2bfloat16(lo);
    __nv_bfloat16 b = __float2bfloat16(hi);
    return ((uint32_t)__bfloat16_as_ushort(b) << 16) | (uint32_t)__bfloat16_as_ushort(a);
}

// mma.sync m16n8k16 row.col f32.bf16.bf16.f32 (sm_80+, plain-target PTX)
#define MMA_BF16(c, a, b)                                                      \
    asm volatile(                                                              \
        "mma.sync.aligned.m16n8k16.row.col.f32.bf16.bf16.f32 "                 \
        "{%0,%1,%2,%3}, {%4,%5,%6,%7}, {%8,%9}, {%0,%1,%2,%3};"                \
        : "+f"((c)[0]), "+f"((c)[1]), "+f"((c)[2]), "+f"((c)[3])               \
        : "r"((a)[0]), "r"((a)[1]), "r"((a)[2]), "r"((a)[3]),                  \
          "r"((b)[0]), "r"((b)[1]))

// =============================================================================
// Tensor-core NT GEMM (fp32 via bf16 hi/lo split, 3 MMAs per k16 step)
//   C[m,n] = sum_k A[m,k] * B[n,k]
//   CTA tile 128(M) x 128(N), K chunk 64. M%128==0, K%64==0 required.
//   Nvalid may be < gridDim.x*128 (x_proj N=96): guarded loads/stores.
//   mode 0: plain store; mode 1: softplus(acc + bias[n])
//   8 warps: warp_m = wid&3 (32 rows), warp_n = wid>>2 (64 cols)
// =============================================================================
#define TILE_BYTES 16384                 // 128 rows x 64 bf16 x 2B (SW128 rows)
#define STAGE_BYTES (4 * TILE_BYTES)     // A_hi, A_lo, B_hi, B_lo
#define TC_SMEM_TOTAL (2 * STAGE_BYTES)  // 128 KB

__global__ void __launch_bounds__(256, 1)
mma_gemm(const float* __restrict__ A, int lda,
         const float* __restrict__ B, int ldb,
         float* __restrict__ C, int ldc,
         int Nvalid, int K,
         const float* __restrict__ bias, int mode)
{
    extern __shared__ char smem[];
    const int tid = threadIdx.x;
    const int wid = tid >> 5;
    const int lane = tid & 31;
    const int m0  = blockIdx.y * 128;
    const int n0  = blockIdx.x * 128;

    const int warp_m = (wid & 3) * 32;   // M offset within CTA tile
    const int warp_n = (wid >> 2) * 64;  // N offset within CTA tile

    const int qrow = lane >> 2;          // 0..7
    const int qcol = (lane & 3) * 2;     // bf16 pair index along k / col

    float acc[2][8][4];
#pragma unroll
    for (int mt = 0; mt < 2; mt++)
#pragma unroll
        for (int nt = 0; nt < 8; nt++)
#pragma unroll
            for (int i = 0; i < 4; i++) acc[mt][nt][i] = 0.f;

    float4 ra[8], rb[8];

    // ---- global load of one 128x64 fp32 tile pair into registers ----
    auto ldg = [&](int k0) {
#pragma unroll
        for (int i = 0; i < 8; i++) {
            int lin = (tid + i * 256) << 2;
            int r   = lin >> 6;
            int col = lin & 63;
            ra[i] = *reinterpret_cast<const float4*>(
                A + (size_t)(m0 + r) * lda + k0 + col);
            int gn = n0 + r;
            rb[i] = make_float4(0.f, 0.f, 0.f, 0.f);
            if (gn < Nvalid)
                rb[i] = *reinterpret_cast<const float4*>(
                    B + (size_t)gn * ldb + k0 + col);
        }
    };
    // ---- convert fp32 -> bf16 hi/lo and store swizzled into stage ----
    auto sts = [&](int buf) {
        char* stage = smem + buf * STAGE_BYTES;
#pragma unroll
        for (int i = 0; i < 8; i++) {
            int lin = (tid + i * 256) << 2;
            int r   = lin >> 6;
            int col = lin & 63;
            uint32_t sw = SMEM_SWIZZLE_128B((uint32_t)(r * 128 + col * 2));
            {
                float4 v = ra[i];
                float hx = __bfloat162float(__float2bfloat16(v.x));
                float hy = __bfloat162float(__float2bfloat16(v.y));
                float hz = __bfloat162float(__float2bfloat16(v.z));
                float hw = __bfloat162float(__float2bfloat16(v.w));
                *reinterpret_cast<uint2*>(stage + sw) =
                    make_uint2(pack_bf16x2(v.x, v.y), pack_bf16x2(v.z, v.w));
                *reinterpret_cast<uint2*>(stage + TILE_BYTES + sw) =
                    make_uint2(pack_bf16x2(v.x - hx, v.y - hy),
                               pack_bf16x2(v.z - hz, v.w - hw));
            }
            {
                float4 v = rb[i];
                float hx = __bfloat162float(__float2bfloat16(v.x));
                float hy = __bfloat162float(__float2bfloat16(v.y));
                float hz = __bfloat162float(__float2bfloat16(v.z));
                float hw = __bfloat162float(__float2bfloat16(v.w));
                *reinterpret_cast<uint2*>(stage + 2 * TILE_BYTES + sw) =
                    make_uint2(pack_bf16x2(v.x, v.y), pack_bf16x2(v.z, v.w));
                *reinterpret_cast<uint2*>(stage + 3 * TILE_BYTES + sw) =
                    make_uint2(pack_bf16x2(v.x - hx, v.y - hy),
                               pack_bf16x2(v.z - hz, v.w - hw));
            }
        }
    };
    // ---- MMA over one staged 64-K chunk ----
    auto mma_chunk = [&](int buf) {
        char* sAh = smem + buf * STAGE_BYTES;
        char* sAl = sAh + TILE_BYTES;
        char* sBh = sAh + 2 * TILE_BYTES;
        char* sBl = sAh + 3 * TILE_BYTES;
#pragma unroll
        for (int ks = 0; ks < 4; ks++) {
            const int k0 = ks * 16;
            // B fragments: 8 n-tiles, 2 regs each, hi + lo
            uint32_t bh[8][2], bl[8][2];
#pragma unroll
            for (int nt = 0; nt < 8; nt++) {
                int n = warp_n + nt * 8 + qrow;
                uint32_t o0 = SMEM_SWIZZLE_128B((uint32_t)(n * 128 + (k0 + qcol) * 2));
                uint32_t o1 = SMEM_SWIZZLE_128B((uint32_t)(n * 128 + (k0 + 8 + qcol) * 2));
                bh[nt][0] = *reinterpret_cast<const uint32_t*>(sBh + o0);
                bh[nt][1] = *reinterpret_cast<const uint32_t*>(sBh + o1);
                bl[nt][0] = *reinterpret_cast<const uint32_t*>(sBl + o0);
                bl[nt][1] = *reinterpret_cast<const uint32_t*>(sBl + o1);
            }
#pragma unroll
            for (int mt = 0; mt < 2; mt++) {
                int r0 = warp_m + mt * 16 + qrow;
                uint32_t oa0 = SMEM_SWIZZLE_128B((uint32_t)( r0      * 128 + (k0 + qcol) * 2));
                uint32_t oa1 = SMEM_SWIZZLE_128B((uint32_t)((r0 + 8) * 128 + (k0 + qcol) * 2));
                uint32_t oa2 = SMEM_SWIZZLE_128B((uint32_t)( r0      * 128 + (k0 + 8 + qcol) * 2));
                uint32_t oa3 = SMEM_SWIZZLE_128B((uint32_t)((r0 + 8) * 128 + (k0 + 8 + qcol) * 2));
                uint32_t ah[4], al[4];
                ah[0] = *reinterpret_cast<const uint32_t*>(sAh + oa0);
                ah[1] = *reinterpret_cast<const uint32_t*>(sAh + oa1);
                ah[2] = *reinterpret_cast<const uint32_t*>(sAh + oa2);
                ah[3] = *reinterpret_cast<const uint32_t*>(sAh + oa3);
                al[0] = *reinterpret_cast<const uint32_t*>(sAl + oa0);
                al[1] = *reinterpret_cast<const uint32_t*>(sAl + oa1);
                al[2] = *reinterpret_cast<const uint32_t*>(sAl + oa2);
                al[3] = *reinterpret_cast<const uint32_t*>(sAl + oa3);
#pragma unroll
                for (int nt = 0; nt < 8; nt++) {
                    MMA_BF16(acc[mt][nt], ah, bh[nt]);
                    MMA_BF16(acc[mt][nt], ah, bl[nt]);
                    MMA_BF16(acc[mt][nt], al, bh[nt]);
                }
            }
        }
    };

    // ---- pipelined mainloop (double-buffered smem) ----
    const int NC = K >> 6;
    ldg(0);
    sts(0);
    __syncthreads();
    for (int c = 1; c < NC; c++) {
        ldg(c << 6);                 // overlap global latency with MMA below
        mma_chunk((c - 1) & 1);
        sts(c & 1);
        __syncthreads();
    }
    mma_chunk((NC - 1) & 1);

    // ---- epilogue: direct fp32 stores from register accumulators ----
#pragma unroll
    for (int mt = 0; mt < 2; mt++) {
        int row0 = m0 + warp_m + mt * 16 + qrow;
        int row1 = row0 + 8;
#pragma unroll
        for (int nt = 0; nt < 8; nt++) {
            int gn = n0 + warp_n + nt * 8 + qcol;
            if (gn >= Nvalid) continue;
            float2 v0 = make_float2(acc[mt][nt][0], acc[mt][nt][1]);
            float2 v1 = make_float2(acc[mt][nt][2], acc[mt][nt][3]);
            if (mode == 1) {
                float b0 = bias[gn], b1 = bias[gn + 1];
                v0.x += b0; v0.y += b1; v1.x += b0; v1.y += b1;
                v0.x = (v0.x > 20.f) ? v0.x : log1pf(expf(v0.x));
                v0.y = (v0.y > 20.f) ? v0.y : log1pf(expf(v0.y));
                v1.x = (v1.x > 20.f) ? v1.x : log1pf(expf(v1.x));
                v1.y = (v1.y > 20.f) ? v1.y : log1pf(expf(v1.y));
            }
            *reinterpret_cast<float2*>(C + (size_t)row0 * ldc + gn) = v0;
            *reinterpret_cast<float2*>(C + (size_t)row1 * ldc + gn) = v1;
        }
    }
}

// ---------------- fused residual-add + LayerNorm -----------------------------
__global__ void resln_kernel(const float* __restrict__ hin,
                             float* __restrict__ res,
                             float* __restrict__ hn,
                             const float* __restrict__ w,
                             const float* __restrict__ b,
                             int first)
{
    const int l   = blockIdx.x;
    const int tid = threadIdx.x;
    float v[4];
    float s = 0.f, sq = 0.f;
#pragma unroll
    for (int i = 0; i < 4; i++) {
        int c = tid + i * 256;
        float x = hin[l * DMODEL + c];
        if (!first) x += res[l * DMODEL + c];
        res[l * DMODEL + c] = x;
        v[i] = x;
        s  += x;
        sq += x * x;
    }
    __shared__ float shs[8], shq[8];
    const int lane = tid & 31, warp = tid >> 5;
#pragma unroll
    for (int o = 16; o > 0; o >>= 1) {
        s  += __shfl_xor_sync(0xffffffffu, s,  o);
        sq += __shfl_xor_sync(0xffffffffu, sq, o);
    }
    if (lane == 0) { shs[warp] = s; shq[warp] = sq; }
    __syncthreads();
    s = 0.f; sq = 0.f;
#pragma unroll
    for (int i = 0; i < 8; i++) { s += shs[i]; sq += shq[i]; }

    const float inv = 1.f / (float)DMODEL;
    const float mu  = s * inv;
    const float var = sq * inv - mu * mu;
    const float rstd = rsqrtf(var + 1e-5f);
#pragma unroll
    for (int i = 0; i < 4; i++) {
        int c = tid + i * 256;
        hn[l * DMODEL + c] = (v[i] - mu) * rstd * w[c] + b[c];
    }
}

// ---------------- causal depthwise conv (D_CONV=4) + SiLU --------------------
__global__ void conv_silu_kernel(const float* __restrict__ xz,
                                 const float* __restrict__ cw,
                                 const float* __restrict__ cb,
                                 float* __restrict__ xconv)
{
    const int idx = blockIdx.x * blockDim.x + threadIdx.x;
    if (idx >= L_SEQ * DINNER) return;
    const int l = idx >> 11;
    const int d = idx & (DINNER - 1);

    float acc = cb[d];
    const float w0 = cw[d*4+0], w1 = cw[d*4+1], w2 = cw[d*4+2], w3 = cw[d*4+3];
    if (l >= 3) acc = fmaf(w0, xz[(size_t)(l-3) * (2*DINNER) + d], acc);
    if (l >= 2) acc = fmaf(w1, xz[(size_t)(l-2) * (2*DINNER) + d], acc);
    if (l >= 1) acc = fmaf(w2, xz[(size_t)(l-1) * (2*DINNER) + d], acc);
    acc = fmaf(w3, xz[(size_t)l * (2*DINNER) + d], acc);

    acc = acc / (1.f + expf(-acc));
    xconv[idx] = acc;
}

// ---------------- selective scan + D-skip + SiLU(z) gate ---------------------
__global__ void scan_kernel(const float* __restrict__ delta,
                            const float* __restrict__ xdbl,
                            const float* __restrict__ xconv,
                            const float* __restrict__ xz,
                            const float* __restrict__ A_log,
                            const float* __restrict__ Dvec,
                            float* __restrict__ y)
{
    const int warp = threadIdx.x >> 5;
    const int lane = threadIdx.x & 31;
    const int grp  = lane >> 4;
    const int s    = lane & 15;
    const int d    = blockIdx.x * 16 + warp * 2 + grp;

    const float a2 = -expf(A_log[d * DSTATE + s]) * 1.4426950408889634f;
    const float Dd = Dvec[d];

    float h = 0.f;
    for (int t = 0; t < L_SEQ; t++) {
        const float dl = delta[(size_t)t * DINNER + d];
        const float xv = xconv[(size_t)t * DINNER + d];
        const float Bs = xdbl[t * XDBL_W + DTRANK + s];
        const float Cs = xdbl[t * XDBL_W + DTRANK + DSTATE + s];

        const float dA = exp2f(dl * a2);
        h = fmaf(dA, h, dl * xv * Bs);

        float acc = h * Cs;
        acc += __shfl_xor_sync(0xffffffffu, acc, 1);
        acc += __shfl_xor_sync(0xffffffffu, acc, 2);
        acc += __shfl_xor_sync(0xffffffffu, acc, 4);
        acc += __shfl_xor_sync(0xffffffffu, acc, 8);

        if (s == 0) {
            const float zv = xz[(size_t)t * (2*DINNER) + DINNER + d];
            float yv = acc + xv * Dd;
            yv *= zv / (1.f + expf(-zv));
            y[(size_t)t * DINNER + d] = yv;
        }
    }
}

// ---------------- host orchestration ----------------------------------------
extern "C" void kernel_launch(void* const* d_in, const int* in_sizes, int n_in,
                              void* d_out, int out_size)
{
    const float* input   = (const float*)d_in[0];
    const float* input_w = (const float*)d_in[2];
    const float* norm_w  = (const float*)d_in[3];
    const float* norm_b  = (const float*)d_in[4];
    const float* ipw     = (const float*)d_in[5];
    const float* cw      = (const float*)d_in[6];
    const float* cb      = (const float*)d_in[7];
    const float* xpw     = (const float*)d_in[8];
    const float* dtw     = (const float*)d_in[9];
    const float* dtb     = (const float*)d_in[10];
    const float* A_log   = (const float*)d_in[11];
    const float* ssm_D   = (const float*)d_in[12];
    const float* opw     = (const float*)d_in[13];

    float *res, *hn, *h, *xz, *xconv, *xdbl, *delta, *y;
    cudaGetSymbolAddress((void**)&res,   g_res);
    cudaGetSymbolAddress((void**)&hn,    g_hn);
    cudaGetSymbolAddress((void**)&h,     g_h);
    cudaGetSymbolAddress((void**)&xz,    g_xz);
    cudaGetSymbolAddress((void**)&xconv, g_xconv);
    cudaGetSymbolAddress((void**)&xdbl,  g_xdbl);
    cudaGetSymbolAddress((void**)&delta, g_delta);
    cudaGetSymbolAddress((void**)&y,     g_y);

    cudaFuncSetAttribute(mma_gemm, cudaFuncAttributeMaxDynamicSharedMemorySize,
                         TC_SMEM_TOTAL);

    // h = input @ input_w^T  [1024,512] x [1024,512]^T
    mma_gemm<<<dim3(DMODEL/128, L_SEQ/128), 256, TC_SMEM_TOTAL>>>(
        input, INLEN, input_w, INLEN, h, DMODEL, DMODEL, INLEN, nullptr, 0);

    for (int i = 0; i < NLAYERS; i++) {
        resln_kernel<<<L_SEQ, 256>>>(h, res, hn,
                                     norm_w + i*DMODEL, norm_b + i*DMODEL, i == 0);

        // xz = hn @ in_proj_w^T  [1024,1024] x [4096,1024]^T
        mma_gemm<<<dim3((2*DINNER)/128, L_SEQ/128), 256, TC_SMEM_TOTAL>>>(
            hn, DMODEL, ipw + (size_t)i*2*DINNER*DMODEL, DMODEL,
            xz, 2*DINNER, 2*DINNER, DMODEL, nullptr, 0);

        conv_silu_kernel<<<(L_SEQ*DINNER)/256, 256>>>(
            xz, cw + (size_t)i*DINNER*4, cb + i*DINNER, xconv);

        // x_dbl = xconv @ x_proj_w^T   (N=96 < 128, guarded)
        mma_gemm<<<dim3(1, L_SEQ/128), 256, TC_SMEM_TOTAL>>>(
            xconv, DINNER, xpw + (size_t)i*XDBL_W*DINNER, DINNER,
            xdbl, XDBL_W, XDBL_W, DINNER, nullptr, 0);

        // delta = softplus(x_dbl[:, :64] @ dt_proj_w^T + dt_bias)   (K=64)
        mma_gemm<<<dim3(DINNER/128, L_SEQ/128), 256, TC_SMEM_TOTAL>>>(
            xdbl, XDBL_W, dtw + (size_t)i*DINNER*DTRANK, DTRANK,
            delta, DINNER, DINNER, DTRANK, dtb + i*DINNER, 1);

        scan_kernel<<<DINNER/16, 256>>>(delta, xdbl, xconv, xz,
                                        A_log + (size_t)i*DINNER*DSTATE,
                                        ssm_D + i*DINNER, y);

        // h(next) = y @ out_proj_w^T  [1024,2048] x [1024,2048]^T
        float* outp = (i == NLAYERS-1) ? (float*)d_out : h;
        mma_gemm<<<dim3(DMODEL/128, L_SEQ/128), 256, TC_SMEM_TOTAL>>>(
            y, DINNER, opw + (size_t)i*DMODEL*DINNER, DINNER,
            outp, DMODEL, DMODEL, DINNER, nullptr, 0);
    }
}

// round 5
// speedup vs baseline: 1.5946x; 1.1485x over previous
#include <cuda_runtime.h>
#include <cuda_bf16.h>
#include <math.h>
#include <stdint.h>

#define L_SEQ   1024
#define INLEN   512
#define DMODEL  1024
#define NLAYERS 4
#define DINNER  2048
#define DSTATE  16
#define DTRANK  64
#define XDBL_W  96   // DT_RANK + 2*D_STATE

typedef __nv_bfloat16 bf16;

// ---------------- fp32 scratch ----------------------------------------------
__device__ float g_res  [L_SEQ * DMODEL];
__device__ float g_h    [L_SEQ * DMODEL];
__device__ float g_xz   [L_SEQ * 2 * DINNER];
__device__ float g_xconv[L_SEQ * DINNER];
__device__ float g_xdbl [L_SEQ * XDBL_W];
__device__ float g_delta[L_SEQ * DINNER];

// ---------------- bf16 hi/lo scratch (split-precision operands) -------------
__device__ bf16 c_in_hi [L_SEQ * INLEN],        c_in_lo [L_SEQ * INLEN];
__device__ bf16 c_inw_hi[DMODEL * INLEN],       c_inw_lo[DMODEL * INLEN];
__device__ bf16 c_ipw_hi[NLAYERS * 2*DINNER * DMODEL], c_ipw_lo[NLAYERS * 2*DINNER * DMODEL];
__device__ bf16 c_xpw_hi[NLAYERS * XDBL_W * DINNER],   c_xpw_lo[NLAYERS * XDBL_W * DINNER];
__device__ bf16 c_dtw_hi[NLAYERS * DINNER * DTRANK],   c_dtw_lo[NLAYERS * DINNER * DTRANK];
__device__ bf16 c_opw_hi[NLAYERS * DMODEL * DINNER],   c_opw_lo[NLAYERS * DMODEL * DINNER];
__device__ bf16 c_hn_hi [L_SEQ * DMODEL],       c_hn_lo [L_SEQ * DMODEL];
__device__ bf16 c_xc_hi [L_SEQ * DINNER],       c_xc_lo [L_SEQ * DINNER];
__device__ bf16 c_xd_hi [L_SEQ * DTRANK],       c_xd_lo [L_SEQ * DTRANK];
__device__ bf16 c_y_hi  [L_SEQ * DINNER],       c_y_lo  [L_SEQ * DINNER];

// ============================ PTX helpers ====================================
__device__ __forceinline__ uint32_t smem_u32(const void* p) {
    uint32_t a;
    asm("{ .reg .u64 t; cvta.to.shared.u64 t, %1; cvt.u32.u64 %0, t; }"
        : "=r"(a) : "l"(p));
    return a;
}
#define CP_ASYNC16(dst, src, sz) \
    asm volatile("cp.async.cg.shared.global [%0], [%1], 16, %2;" \
                 :: "r"(dst), "l"(src), "r"(sz))
#define CP_COMMIT() asm volatile("cp.async.commit_group;" ::: "memory")
#define CP_WAIT(n)  asm volatile("cp.async.wait_group %0;" :: "n"(n) : "memory")

#define LDM4(r0, r1, r2, r3, addr) \
    asm volatile("ldmatrix.sync.aligned.m8n8.x4.shared.b16 {%0,%1,%2,%3}, [%4];" \
                 : "=r"(r0), "=r"(r1), "=r"(r2), "=r"(r3) : "r"(addr))

#define MMA_BF16(c, a, b)                                                      \
    asm volatile(                                                              \
        "mma.sync.aligned.m16n8k16.row.col.f32.bf16.bf16.f32 "                 \
        "{%0,%1,%2,%3}, {%4,%5,%6,%7}, {%8,%9}, {%0,%1,%2,%3};"                \
        : "+f"((c)[0]), "+f"((c)[1]), "+f"((c)[2]), "+f"((c)[3])               \
        : "r"((a)[0]), "r"((a)[1]), "r"((a)[2]), "r"((a)[3]),                  \
          "r"((b)[0]), "r"((b)[1]))

__device__ __forceinline__ uint32_t swz(uint32_t off) {
    return off ^ ((off >> 3) & 0x70);
}
__device__ __forceinline__ void split_bf16(float v, bf16& hi, bf16& lo) {
    hi = __float2bfloat16(v);
    lo = __float2bfloat16(v - __bfloat162float(hi));
}

// =============================================================================
// bf16 hi/lo split-precision NT GEMM (3 MMAs per k16):
//   C[m,n] = sum_k A[m,k]*B[n,k],  fp32-accurate to ~1.5e-5 rel
//   BN = 128 fixed; BM = 128 (WMW=4, NT=8) or 64 (WMW=2, NT=4); K chunk 64.
//   A given as Ahi/Alo bf16 (lda elems), B as Bhi/Blo bf16 (ldb elems).
//   mode 0: plain fp32 store; mode 1: softplus(acc + bias[n]).
// =============================================================================
template<int BM, int WMW, int NT>
__global__ void __launch_bounds__(256, 1)
mma_gemm(const bf16* __restrict__ Ahi, const bf16* __restrict__ Alo, int lda,
         const bf16* __restrict__ Bhi, const bf16* __restrict__ Blo, int ldb,
         float* __restrict__ C, int ldc,
         int Nvalid, int K,
         const float* __restrict__ bias, int mode)
{
    constexpr int ABYTES = BM * 128;           // one A tile (BM x 64 bf16)
    constexpr int BBYTES = 128 * 128;          // one B tile
    constexpr int STAGE  = 2 * ABYTES + 2 * BBYTES;
    constexpr int A_ITER = (BM * 8) / 256;     // 16B units per thread per A tile
    constexpr int B_ITER = 4;

    extern __shared__ char smem[];
    const uint32_t sb = smem_u32(smem);

    const int tid  = threadIdx.x;
    const int wid  = tid >> 5;
    const int lane = tid & 31;
    const int m0   = blockIdx.y * BM;
    const int n0   = blockIdx.x * 128;

    const int warp_m = (wid % WMW) * 32;
    const int warp_n = (wid / WMW) * (NT * 8);

    float acc[2][NT][4];
#pragma unroll
    for (int mt = 0; mt < 2; mt++)
#pragma unroll
        for (int nt = 0; nt < NT; nt++)
#pragma unroll
            for (int i = 0; i < 4; i++) acc[mt][nt][i] = 0.f;

    // ---- stage loader: cp.async one 64-K chunk into buffer buf ----
    auto stage_load = [&](int c, int buf) {
        const int k0 = c << 6;
        const uint32_t st = sb + buf * STAGE;
#pragma unroll
        for (int i = 0; i < A_ITER; i++) {
            int j = tid + i * 256;
            int r = j >> 3, u = j & 7;
            uint32_t so = swz((uint32_t)(r * 128 + u * 16));
            const char* ga = (const char*)(Ahi + (size_t)(m0 + r) * lda + k0 + u * 8);
            const char* gl = (const char*)(Alo + (size_t)(m0 + r) * lda + k0 + u * 8);
            CP_ASYNC16(st + so, ga, 16);
            CP_ASYNC16(st + ABYTES + so, gl, 16);
        }
#pragma unroll
        for (int i = 0; i < B_ITER; i++) {
            int j = tid + i * 256;
            int r = j >> 3, u = j & 7;
            int gn = n0 + r;
            int sz = (gn < Nvalid) ? 16 : 0;
            int gc = (gn < Nvalid) ? gn : 0;
            uint32_t so = swz((uint32_t)(r * 128 + u * 16));
            const char* gb = (const char*)(Bhi + (size_t)gc * ldb + k0 + u * 8);
            const char* gl = (const char*)(Blo + (size_t)gc * ldb + k0 + u * 8);
            CP_ASYNC16(st + 2 * ABYTES + so, gb, sz);
            CP_ASYNC16(st + 2 * ABYTES + BBYTES + so, gl, sz);
        }
        CP_COMMIT();
    };

    // ---- MMA over one staged chunk ----
    auto mma_chunk = [&](int buf) {
        const uint32_t st  = sb + buf * STAGE;
        const uint32_t sAh = st;
        const uint32_t sAl = st + ABYTES;
        const uint32_t sBh = st + 2 * ABYTES;
        const uint32_t sBl = sBh + BBYTES;
#pragma unroll
        for (int ks = 0; ks < 4; ks++) {
            const int kb = ks * 32;   // byte offset of this k16 within 128B row
            uint32_t bh[NT][2], bl[NT][2];
#pragma unroll
            for (int p = 0; p < NT / 2; p++) {
                int row = warp_n + p * 16 + ((lane >> 4) << 3) + (lane & 7);
                int kbyte = kb + ((lane >> 3) & 1) * 16;
                uint32_t off = swz((uint32_t)(row * 128 + kbyte));
                LDM4(bh[2*p][0], bh[2*p][1], bh[2*p+1][0], bh[2*p+1][1], sBh + off);
                LDM4(bl[2*p][0], bl[2*p][1], bl[2*p+1][0], bl[2*p+1][1], sBl + off);
            }
#pragma unroll
            for (int mt = 0; mt < 2; mt++) {
                int row = warp_m + mt * 16 + (lane & 15);
                int kbyte = kb + (lane >> 4) * 16;
                uint32_t off = swz((uint32_t)(row * 128 + kbyte));
                uint32_t ah[4], al[4];
                LDM4(ah[0], ah[1], ah[2], ah[3], sAh + off);
                LDM4(al[0], al[1], al[2], al[3], sAl + off);
#pragma unroll
                for (int nt = 0; nt < NT; nt++) {
                    MMA_BF16(acc[mt][nt], ah, bh[nt]);
                    MMA_BF16(acc[mt][nt], ah, bl[nt]);
                    MMA_BF16(acc[mt][nt], al, bh[nt]);
                }
            }
        }
    };

    // ---- 2-stage cp.async pipeline ----
    const int NC = K >> 6;
    stage_load(0, 0);
    if (NC > 1) stage_load(1, 1);
    for (int c = 0; c < NC; c++) {
        if (c == NC - 1) { CP_WAIT(0); } else { CP_WAIT(1); }
        __syncthreads();
        mma_chunk(c & 1);
        __syncthreads();
        if (c + 2 < NC) stage_load(c + 2, c & 1);
    }

    // ---- epilogue ----
    const int qrow = lane >> 2;
    const int qcol = (lane & 3) * 2;
#pragma unroll
    for (int mt = 0; mt < 2; mt++) {
        int row0 = m0 + warp_m + mt * 16 + qrow;
        int row1 = row0 + 8;
#pragma unroll
        for (int nt = 0; nt < NT; nt++) {
            int gn = n0 + warp_n + nt * 8 + qcol;
            if (gn >= Nvalid) continue;
            float2 v0 = make_float2(acc[mt][nt][0], acc[mt][nt][1]);
            float2 v1 = make_float2(acc[mt][nt][2], acc[mt][nt][3]);
            if (mode == 1) {
                float b0 = bias[gn], b1 = bias[gn + 1];
                v0.x += b0; v0.y += b1; v1.x += b0; v1.y += b1;
                v0.x = (v0.x > 20.f) ? v0.x : log1pf(expf(v0.x));
                v0.y = (v0.y > 20.f) ? v0.y : log1pf(expf(v0.y));
                v1.x = (v1.x > 20.f) ? v1.x : log1pf(expf(v1.x));
                v1.y = (v1.y > 20.f) ? v1.y : log1pf(expf(v1.y));
            }
            *reinterpret_cast<float2*>(C + (size_t)row0 * ldc + gn) = v0;
            *reinterpret_cast<float2*>(C + (size_t)row1 * ldc + gn) = v1;
        }
    }
}

// ---------------- fp32 -> bf16 hi/lo split converter -------------------------
__global__ void cvt_kernel(const float* __restrict__ src,
                           bf16* __restrict__ hi, bf16* __restrict__ lo, int n4)
{
    int i = blockIdx.x * blockDim.x + threadIdx.x;
    if (i >= n4) return;
    float4 v = reinterpret_cast<const float4*>(src)[i];
    bf16 h0, h1, h2, h3, l0, l1, l2, l3;
    split_bf16(v.x, h0, l0); split_bf16(v.y, h1, l1);
    split_bf16(v.z, h2, l2); split_bf16(v.w, h3, l3);
    uint32_t hA = ((uint32_t)__bfloat16_as_ushort(h1) << 16) | __bfloat16_as_ushort(h0);
    uint32_t hB = ((uint32_t)__bfloat16_as_ushort(h3) << 16) | __bfloat16_as_ushort(h2);
    uint32_t lA = ((uint32_t)__bfloat16_as_ushort(l1) << 16) | __bfloat16_as_ushort(l0);
    uint32_t lB = ((uint32_t)__bfloat16_as_ushort(l3) << 16) | __bfloat16_as_ushort(l2);
    reinterpret_cast<uint2*>(hi)[i] = make_uint2(hA, hB);
    reinterpret_cast<uint2*>(lo)[i] = make_uint2(lA, lB);
}

// extract dt columns (first 64 of xdbl row) -> bf16 hi/lo [1024 x 64]
__global__ void cvt_xdbl_kernel(const float* __restrict__ xdbl,
                                bf16* __restrict__ hi, bf16* __restrict__ lo)
{
    int i = blockIdx.x * blockDim.x + threadIdx.x;   // 1024*64 elems
    int r = i >> 6, c = i & 63;
    float v = xdbl[r * XDBL_W + c];
    bf16 h, l; split_bf16(v, h, l);
    hi[i] = h; lo[i] = l;
}

// ---------------- fused residual-add + LayerNorm (emits bf16 hi/lo) ---------
__global__ void resln_kernel(const float* __restrict__ hin,
                             float* __restrict__ res,
                             bf16* __restrict__ hn_hi, bf16* __restrict__ hn_lo,
                             const float* __restrict__ w,
                             const float* __restrict__ b,
                             int first)
{
    const int l   = blockIdx.x;
    const int tid = threadIdx.x;
    float v[4];
    float s = 0.f, sq = 0.f;
#pragma unroll
    for (int i = 0; i < 4; i++) {
        int c = tid + i * 256;
        float x = hin[l * DMODEL + c];
        if (!first) x += res[l * DMODEL + c];
        res[l * DMODEL + c] = x;
        v[i] = x;
        s  += x;
        sq += x * x;
    }
    __shared__ float shs[8], shq[8];
    const int lane = tid & 31, warp = tid >> 5;
#pragma unroll
    for (int o = 16; o > 0; o >>= 1) {
        s  += __shfl_xor_sync(0xffffffffu, s,  o);
        sq += __shfl_xor_sync(0xffffffffu, sq, o);
    }
    if (lane == 0) { shs[warp] = s; shq[warp] = sq; }
    __syncthreads();
    s = 0.f; sq = 0.f;
#pragma unroll
    for (int i = 0; i < 8; i++) { s += shs[i]; sq += shq[i]; }

    const float inv = 1.f / (float)DMODEL;
    const float mu  = s * inv;
    const float var = sq * inv - mu * mu;
    const float rstd = rsqrtf(var + 1e-5f);
#pragma unroll
    for (int i = 0; i < 4; i++) {
        int c = tid + i * 256;
        float o = (v[i] - mu) * rstd * w[c] + b[c];
        bf16 h, lo; split_bf16(o, h, lo);
        hn_hi[l * DMODEL + c] = h;
        hn_lo[l * DMODEL + c] = lo;
    }
}

// ---------------- causal depthwise conv + SiLU (emits fp32 + bf16 hi/lo) -----
__global__ void conv_silu_kernel(const float* __restrict__ xz,
                                 const float* __restrict__ cw,
                                 const float* __restrict__ cb,
                                 float* __restrict__ xconv,
                                 bf16* __restrict__ xc_hi,
                                 bf16* __restrict__ xc_lo)
{
    const int idx = blockIdx.x * blockDim.x + threadIdx.x;
    if (idx >= L_SEQ * DINNER) return;
    const int l = idx >> 11;
    const int d = idx & (DINNER - 1);

    float acc = cb[d];
    const float w0 = cw[d*4+0], w1 = cw[d*4+1], w2 = cw[d*4+2], w3 = cw[d*4+3];
    if (l >= 3) acc = fmaf(w0, xz[(size_t)(l-3) * (2*DINNER) + d], acc);
    if (l >= 2) acc = fmaf(w1, xz[(size_t)(l-2) * (2*DINNER) + d], acc);
    if (l >= 1) acc = fmaf(w2, xz[(size_t)(l-1) * (2*DINNER) + d], acc);
    acc = fmaf(w3, xz[(size_t)l * (2*DINNER) + d], acc);

    acc = acc / (1.f + expf(-acc));
    xconv[idx] = acc;
    bf16 h, lo; split_bf16(acc, h, lo);
    xc_hi[idx] = h;
    xc_lo[idx] = lo;
}

// ---------------- selective scan + D-skip + SiLU(z) gate (emits y hi/lo) -----
__global__ void scan_kernel(const float* __restrict__ delta,
                            const float* __restrict__ xdbl,
                            const float* __restrict__ xconv,
                            const float* __restrict__ xz,
                            const float* __restrict__ A_log,
                            const float* __restrict__ Dvec,
                            bf16* __restrict__ y_hi,
                            bf16* __restrict__ y_lo)
{
    const int warp = threadIdx.x >> 5;
    const int lane = threadIdx.x & 31;
    const int grp  = lane >> 4;
    const int s    = lane & 15;
    const int d    = blockIdx.x * 16 + warp * 2 + grp;

    const float a2 = -expf(A_log[d * DSTATE + s]) * 1.4426950408889634f;
    const float Dd = Dvec[d];

    float h = 0.f;
    for (int t = 0; t < L_SEQ; t++) {
        const float dl = delta[(size_t)t * DINNER + d];
        const float xv = xconv[(size_t)t * DINNER + d];
        const float Bs = xdbl[t * XDBL_W + DTRANK + s];
        const float Cs = xdbl[t * XDBL_W + DTRANK + DSTATE + s];

        const float dA = exp2f(dl * a2);
        h = fmaf(dA, h, dl * xv * Bs);

        float acc = h * Cs;
        acc += __shfl_xor_sync(0xffffffffu, acc, 1);
        acc += __shfl_xor_sync(0xffffffffu, acc, 2);
        acc += __shfl_xor_sync(0xffffffffu, acc, 4);
        acc += __shfl_xor_sync(0xffffffffu, acc, 8);

        if (s == 0) {
            const float zv = xz[(size_t)t * (2*DINNER) + DINNER + d];
            float yv = acc + xv * Dd;
            yv *= zv / (1.f + expf(-zv));
            bf16 yh, yl; split_bf16(yv, yh, yl);
            y_hi[(size_t)t * DINNER + d] = yh;
            y_lo[(size_t)t * DINNER + d] = yl;
        }
    }
}

// ---------------- host orchestration ----------------------------------------
extern "C" void kernel_launch(void* const* d_in, const int* in_sizes, int n_in,
                              void* d_out, int out_size)
{
    const float* input   = (const float*)d_in[0];
    const float* input_w = (const float*)d_in[2];
    const float* norm_w  = (const float*)d_in[3];
    const float* norm_b  = (const float*)d_in[4];
    const float* ipw     = (const float*)d_in[5];
    const float* cw      = (const float*)d_in[6];
    const float* cb      = (const float*)d_in[7];
    const float* xpw     = (const float*)d_in[8];
    const float* dtw     = (const float*)d_in[9];
    const float* dtb     = (const float*)d_in[10];
    const float* A_log   = (const float*)d_in[11];
    const float* ssm_D   = (const float*)d_in[12];
    const float* opw     = (const float*)d_in[13];

    float *res, *h, *xz, *xconv, *xdbl, *delta;
    cudaGetSymbolAddress((void**)&res,   g_res);
    cudaGetSymbolAddress((void**)&h,     g_h);
    cudaGetSymbolAddress((void**)&xz,    g_xz);
    cudaGetSymbolAddress((void**)&xconv, g_xconv);
    cudaGetSymbolAddress((void**)&xdbl,  g_xdbl);
    cudaGetSymbolAddress((void**)&delta, g_delta);

    bf16 *in_hi, *in_lo, *inw_hi, *inw_lo, *ipw_hi, *ipw_lo, *xpw_hi, *xpw_lo;
    bf16 *dtw_hi, *dtw_lo, *opw_hi, *opw_lo, *hn_hi, *hn_lo, *xc_hi, *xc_lo;
    bf16 *xd_hi, *xd_lo, *y_hi, *y_lo;
    cudaGetSymbolAddress((void**)&in_hi,  c_in_hi);  cudaGetSymbolAddress((void**)&in_lo,  c_in_lo);
    cudaGetSymbolAddress((void**)&inw_hi, c_inw_hi); cudaGetSymbolAddress((void**)&inw_lo, c_inw_lo);
    cudaGetSymbolAddress((void**)&ipw_hi, c_ipw_hi); cudaGetSymbolAddress((void**)&ipw_lo, c_ipw_lo);
    cudaGetSymbolAddress((void**)&xpw_hi, c_xpw_hi); cudaGetSymbolAddress((void**)&xpw_lo, c_xpw_lo);
    cudaGetSymbolAddress((void**)&dtw_hi, c_dtw_hi); cudaGetSymbolAddress((void**)&dtw_lo, c_dtw_lo);
    cudaGetSymbolAddress((void**)&opw_hi, c_opw_hi); cudaGetSymbolAddress((void**)&opw_lo, c_opw_lo);
    cudaGetSymbolAddress((void**)&hn_hi,  c_hn_hi);  cudaGetSymbolAddress((void**)&hn_lo,  c_hn_lo);
    cudaGetSymbolAddress((void**)&xc_hi,  c_xc_hi);  cudaGetSymbolAddress((void**)&xc_lo,  c_xc_lo);
    cudaGetSymbolAddress((void**)&xd_hi,  c_xd_hi);  cudaGetSymbolAddress((void**)&xd_lo,  c_xd_lo);
    cudaGetSymbolAddress((void**)&y_hi,   c_y_hi);   cudaGetSymbolAddress((void**)&y_lo,   c_y_lo);

    // GEMM instantiations + smem opt-in
    auto g128 = mma_gemm<128, 4, 8>;   // 128x128 tile, 2 x 64KB stages
    auto g64  = mma_gemm<64, 2, 4>;    // 64x128 tile,  2 x 48KB stages
    cudaFuncSetAttribute(g128, cudaFuncAttributeMaxDynamicSharedMemorySize, 131072);
    cudaFuncSetAttribute(g64,  cudaFuncAttributeMaxDynamicSharedMemorySize, 98304);

    // ---- upfront conversions (weights + input) ----
    cvt_kernel<<<(L_SEQ*INLEN/4 + 255)/256, 256>>>(input, in_hi, in_lo, L_SEQ*INLEN/4);
    cvt_kernel<<<(DMODEL*INLEN/4 + 255)/256, 256>>>(input_w, inw_hi, inw_lo, DMODEL*INLEN/4);
    cvt_kernel<<<(NLAYERS*2*DINNER*DMODEL/4 + 255)/256, 256>>>(ipw, ipw_hi, ipw_lo, NLAYERS*2*DINNER*DMODEL/4);
    cvt_kernel<<<(NLAYERS*XDBL_W*DINNER/4 + 255)/256, 256>>>(xpw, xpw_hi, xpw_lo, NLAYERS*XDBL_W*DINNER/4);
    cvt_kernel<<<(NLAYERS*DINNER*DTRANK/4 + 255)/256, 256>>>(dtw, dtw_hi, dtw_lo, NLAYERS*DINNER*DTRANK/4);
    cvt_kernel<<<(NLAYERS*DMODEL*DINNER/4 + 255)/256, 256>>>(opw, opw_hi, opw_lo, NLAYERS*DMODEL*DINNER/4);

    // h = input @ input_w^T  [1024,512]x[1024,512]^T  (BM=64 -> 128 CTAs)
    g64<<<dim3(DMODEL/128, L_SEQ/64), 256, 98304>>>(
        in_hi, in_lo, INLEN, inw_hi, inw_lo, INLEN, h, DMODEL,
        DMODEL, INLEN, nullptr, 0);

    for (int i = 0; i < NLAYERS; i++) {
        resln_kernel<<<L_SEQ, 256>>>(h, res, hn_hi, hn_lo,
                                     norm_w + i*DMODEL, norm_b + i*DMODEL, i == 0);

        // xz = hn @ in_proj_w^T   (256 CTAs, BM=128)
        g128<<<dim3((2*DINNER)/128, L_SEQ/128), 256, 131072>>>(
            hn_hi, hn_lo, DMODEL,
            ipw_hi + (size_t)i*2*DINNER*DMODEL, ipw_lo + (size_t)i*2*DINNER*DMODEL, DMODEL,
            xz, 2*DINNER, 2*DINNER, DMODEL, nullptr, 0);

        conv_silu_kernel<<<(L_SEQ*DINNER)/256, 256>>>(
            xz, cw + (size_t)i*DINNER*4, cb + i*DINNER, xconv, xc_hi, xc_lo);

        // x_dbl = xconv @ x_proj_w^T   (N=96, BM=64 -> 16 CTAs, K=2048)
        g64<<<dim3(1, L_SEQ/64), 256, 98304>>>(
            xc_hi, xc_lo, DINNER,
            xpw_hi + (size_t)i*XDBL_W*DINNER, xpw_lo + (size_t)i*XDBL_W*DINNER, DINNER,
            xdbl, XDBL_W, XDBL_W, DINNER, nullptr, 0);

        cvt_xdbl_kernel<<<(L_SEQ*DTRANK)/256, 256>>>(xdbl, xd_hi, xd_lo);

        // delta = softplus(xd @ dt_proj_w^T + dt_bias)  (K=64, 128 CTAs)
        g128<<<dim3(DINNER/128, L_SEQ/128), 256, 131072>>>(
            xd_hi, xd_lo, DTRANK,
            dtw_hi + (size_t)i*DINNER*DTRANK, dtw_lo + (size_t)i*DINNER*DTRANK, DTRANK,
            delta, DINNER, DINNER, DTRANK, dtb + i*DINNER, 1);

        scan_kernel<<<DINNER/16, 256>>>(delta, xdbl, xconv, xz,
                                        A_log + (size_t)i*DINNER*DSTATE,
                                        ssm_D + i*DINNER, y_hi, y_lo);

        // h(next) = y @ out_proj_w^T  (BM=64 -> 128 CTAs, K=2048)
        float* outp = (i == NLAYERS-1) ? (float*)d_out : h;
        g64<<<dim3(DMODEL/128, L_SEQ/64), 256, 98304>>>(
            y_hi, y_lo, DINNER,
            opw_hi + (size_t)i*DMODEL*DINNER, opw_lo + (size_t)i*DMODEL*DINNER, DINNER,
            outp, DMODEL, DMODEL, DINNER, nullptr, 0);
    }
}

// round 6
// speedup vs baseline: 1.6098x; 1.0095x over previous
#include <cuda_runtime.h>
#include <cuda_bf16.h>
#include <math.h>
#include <stdint.h>

#define L_SEQ   1024
#define INLEN   512
#define DMODEL  1024
#define NLAYERS 4
#define DINNER  2048
#define DSTATE  16
#define DTRANK  64
#define XDBL_W  96   // DT_RANK + 2*D_STATE

typedef __nv_bfloat16 bf16;

// ---------------- fp32 scratch ----------------------------------------------
__device__ float g_res  [L_SEQ * DMODEL];
__device__ float g_h    [L_SEQ * DMODEL];
__device__ float g_xz   [L_SEQ * 2 * DINNER];
__device__ float g_xconv[L_SEQ * DINNER];
__device__ float g_xdbl [L_SEQ * XDBL_W];
__device__ float g_delta[L_SEQ * DINNER];

// ---------------- bf16 hi/lo scratch (split-precision operands) -------------
__device__ bf16 c_in_hi [L_SEQ * INLEN],        c_in_lo [L_SEQ * INLEN];
__device__ bf16 c_inw_hi[DMODEL * INLEN],       c_inw_lo[DMODEL * INLEN];
__device__ bf16 c_ipw_hi[NLAYERS * 2*DINNER * DMODEL], c_ipw_lo[NLAYERS * 2*DINNER * DMODEL];
__device__ bf16 c_xpw_hi[NLAYERS * XDBL_W * DINNER],   c_xpw_lo[NLAYERS * XDBL_W * DINNER];
__device__ bf16 c_dtw_hi[NLAYERS * DINNER * DTRANK],   c_dtw_lo[NLAYERS * DINNER * DTRANK];
__device__ bf16 c_opw_hi[NLAYERS * DMODEL * DINNER],   c_opw_lo[NLAYERS * DMODEL * DINNER];
__device__ bf16 c_hn_hi [L_SEQ * DMODEL],       c_hn_lo [L_SEQ * DMODEL];
__device__ bf16 c_xc_hi [L_SEQ * DINNER],       c_xc_lo [L_SEQ * DINNER];
__device__ bf16 c_xd_hi [L_SEQ * DTRANK],       c_xd_lo [L_SEQ * DTRANK];
__device__ bf16 c_y_hi  [L_SEQ * DINNER],       c_y_lo  [L_SEQ * DINNER];

// ============================ PTX helpers ====================================
__device__ __forceinline__ uint32_t smem_u32(const void* p) {
    uint32_t a;
    asm("{ .reg .u64 t; cvta.to.shared.u64 t, %1; cvt.u32.u64 %0, t; }"
        : "=r"(a) : "l"(p));
    return a;
}
#define CP_ASYNC16(dst, src, sz) \
    asm volatile("cp.async.cg.shared.global [%0], [%1], 16, %2;" \
                 :: "r"(dst), "l"(src), "r"(sz))
#define CP_COMMIT() asm volatile("cp.async.commit_group;" ::: "memory")
#define CP_WAIT0()  asm volatile("cp.async.wait_group 0;" ::: "memory")

#define LDM4(r0, r1, r2, r3, addr) \
    asm volatile("ldmatrix.sync.aligned.m8n8.x4.shared.b16 {%0,%1,%2,%3}, [%4];" \
                 : "=r"(r0), "=r"(r1), "=r"(r2), "=r"(r3) : "r"(addr))

#define MMA_BF16(c, a, b)                                                      \
    asm volatile(                                                              \
        "mma.sync.aligned.m16n8k16.row.col.f32.bf16.bf16.f32 "                 \
        "{%0,%1,%2,%3}, {%4,%5,%6,%7}, {%8,%9}, {%0,%1,%2,%3};"                \
        : "+f"((c)[0]), "+f"((c)[1]), "+f"((c)[2]), "+f"((c)[3])               \
        : "r"((a)[0]), "r"((a)[1]), "r"((a)[2]), "r"((a)[3]),                  \
          "r"((b)[0]), "r"((b)[1]))

__device__ __forceinline__ uint32_t swz(uint32_t off) {
    return off ^ ((off >> 3) & 0x70);
}
__device__ __forceinline__ void split_bf16(float v, bf16& hi, bf16& lo) {
    hi = __float2bfloat16(v);
    lo = __float2bfloat16(v - __bfloat162float(hi));
}

// =============================================================================
// bf16 hi/lo split-precision NT GEMM (3 MMAs per k16):
//   C[m,n] = sum_k A[m,k]*B[n,k]
//   BN = 128 fixed; BM = 128 (WMW=4, NT=8) or 64 (WMW=2, NT=4); K chunk 64.
//   mode 0: plain fp32 store; mode 1: softplus(acc + bias[n]).
// =============================================================================
template<int BM, int WMW, int NT>
__global__ void __launch_bounds__(256, 1)
mma_gemm(const bf16* __restrict__ Ahi, const bf16* __restrict__ Alo, int lda,
         const bf16* __restrict__ Bhi, const bf16* __restrict__ Blo, int ldb,
         float* __restrict__ C, int ldc,
         int Nvalid, int K,
         const float* __restrict__ bias, int mode)
{
    constexpr int ABYTES = BM * 128;           // one A tile (BM x 64 bf16)
    constexpr int BBYTES = 128 * 128;          // one B tile
    constexpr int STAGE  = 2 * ABYTES + 2 * BBYTES;
    constexpr int A_ITER = (BM * 8) / 256;
    constexpr int B_ITER = 4;

    extern __shared__ char smem[];
    const uint32_t sb = smem_u32(smem);

    const int tid  = threadIdx.x;
    const int wid  = tid >> 5;
    const int lane = tid & 31;
    const int m0   = blockIdx.y * BM;
    const int n0   = blockIdx.x * 128;

    const int warp_m = (wid % WMW) * 32;
    const int warp_n = (wid / WMW) * (NT * 8);

    float acc[2][NT][4];
#pragma unroll
    for (int mt = 0; mt < 2; mt++)
#pragma unroll
        for (int nt = 0; nt < NT; nt++)
#pragma unroll
            for (int i = 0; i < 4; i++) acc[mt][nt][i] = 0.f;

    auto stage_load = [&](int c, int buf) {
        const int k0 = c << 6;
        const uint32_t st = sb + buf * STAGE;
#pragma unroll
        for (int i = 0; i < A_ITER; i++) {
            int j = tid + i * 256;
            int r = j >> 3, u = j & 7;
            uint32_t so = swz((uint32_t)(r * 128 + u * 16));
            const char* ga = (const char*)(Ahi + (size_t)(m0 + r) * lda + k0 + u * 8);
            const char* gl = (const char*)(Alo + (size_t)(m0 + r) * lda + k0 + u * 8);
            CP_ASYNC16(st + so, ga, 16);
            CP_ASYNC16(st + ABYTES + so, gl, 16);
        }
#pragma unroll
        for (int i = 0; i < B_ITER; i++) {
            int j = tid + i * 256;
            int r = j >> 3, u = j & 7;
            int gn = n0 + r;
            int sz = (gn < Nvalid) ? 16 : 0;
            int gc = (gn < Nvalid) ? gn : 0;
            uint32_t so = swz((uint32_t)(r * 128 + u * 16));
            const char* gb = (const char*)(Bhi + (size_t)gc * ldb + k0 + u * 8);
            const char* gl = (const char*)(Blo + (size_t)gc * ldb + k0 + u * 8);
            CP_ASYNC16(st + 2 * ABYTES + so, gb, sz);
            CP_ASYNC16(st + 2 * ABYTES + BBYTES + so, gl, sz);
        }
        CP_COMMIT();
    };

    auto mma_chunk = [&](int buf) {
        const uint32_t st  = sb + buf * STAGE;
        const uint32_t sAh = st;
        const uint32_t sAl = st + ABYTES;
        const uint32_t sBh = st + 2 * ABYTES;
        const uint32_t sBl = sBh + BBYTES;
#pragma unroll
        for (int ks = 0; ks < 4; ks++) {
            const int kb = ks * 32;
            uint32_t bh[NT][2], bl[NT][2];
#pragma unroll
            for (int p = 0; p < NT / 2; p++) {
                int row = warp_n + p * 16 + ((lane >> 4) << 3) + (lane & 7);
                int kbyte = kb + ((lane >> 3) & 1) * 16;
                uint32_t off = swz((uint32_t)(row * 128 + kbyte));
                LDM4(bh[2*p][0], bh[2*p][1], bh[2*p+1][0], bh[2*p+1][1], sBh + off);
                LDM4(bl[2*p][0], bl[2*p][1], bl[2*p+1][0], bl[2*p+1][1], sBl + off);
            }
#pragma unroll
            for (int mt = 0; mt < 2; mt++) {
                int row = warp_m + mt * 16 + (lane & 15);
                int kbyte = kb + (lane >> 4) * 16;
                uint32_t off = swz((uint32_t)(row * 128 + kbyte));
                uint32_t ah[4], al[4];
                LDM4(ah[0], ah[1], ah[2], ah[3], sAh + off);
                LDM4(al[0], al[1], al[2], al[3], sAl + off);
                // three independent sweeps: consecutive MMAs hit different acc
#pragma unroll
                for (int nt = 0; nt < NT; nt++) MMA_BF16(acc[mt][nt], ah, bh[nt]);
#pragma unroll
                for (int nt = 0; nt < NT; nt++) MMA_BF16(acc[mt][nt], ah, bl[nt]);
#pragma unroll
                for (int nt = 0; nt < NT; nt++) MMA_BF16(acc[mt][nt], al, bh[nt]);
            }
        }
    };

    // ---- pipeline: 1 barrier per chunk, prefetch in flight during MMA ----
    const int NC = K >> 6;
    stage_load(0, 0);
    for (int c = 0; c < NC; c++) {
        CP_WAIT0();              // own cp.async groups (chunk <= c) complete
        __syncthreads();         // chunk c visible; mma(c-1) finished everywhere
        if (c + 1 < NC) stage_load(c + 1, (c + 1) & 1);  // flies during mma(c)
        mma_chunk(c & 1);
    }

    // ---- epilogue ----
    const int qrow = lane >> 2;
    const int qcol = (lane & 3) * 2;
#pragma unroll
    for (int mt = 0; mt < 2; mt++) {
        int row0 = m0 + warp_m + mt * 16 + qrow;
        int row1 = row0 + 8;
#pragma unroll
        for (int nt = 0; nt < NT; nt++) {
            int gn = n0 + warp_n + nt * 8 + qcol;
            if (gn >= Nvalid) continue;
            float2 v0 = make_float2(acc[mt][nt][0], acc[mt][nt][1]);
            float2 v1 = make_float2(acc[mt][nt][2], acc[mt][nt][3]);
            if (mode == 1) {
                float b0 = bias[gn], b1 = bias[gn + 1];
                v0.x += b0; v0.y += b1; v1.x += b0; v1.y += b1;
                v0.x = (v0.x > 20.f) ? v0.x : log1pf(expf(v0.x));
                v0.y = (v0.y > 20.f) ? v0.y : log1pf(expf(v0.y));
                v1.x = (v1.x > 20.f) ? v1.x : log1pf(expf(v1.x));
                v1.y = (v1.y > 20.f) ? v1.y : log1pf(expf(v1.y));
            }
            *reinterpret_cast<float2*>(C + (size_t)row0 * ldc + gn) = v0;
            *reinterpret_cast<float2*>(C + (size_t)row1 * ldc + gn) = v1;
        }
    }
}

// ---------------- fp32 -> bf16 hi/lo split converters ------------------------
__global__ void cvt_kernel(const float* __restrict__ src,
                           bf16* __restrict__ hi, bf16* __restrict__ lo, int n4)
{
    int i = blockIdx.x * blockDim.x + threadIdx.x;
    if (i >= n4) return;
    float4 v = reinterpret_cast<const float4*>(src)[i];
    bf16 h0, h1, h2, h3, l0, l1, l2, l3;
    split_bf16(v.x, h0, l0); split_bf16(v.y, h1, l1);
    split_bf16(v.z, h2, l2); split_bf16(v.w, h3, l3);
    uint32_t hA = ((uint32_t)__bfloat16_as_ushort(h1) << 16) | __bfloat16_as_ushort(h0);
    uint32_t hB = ((uint32_t)__bfloat16_as_ushort(h3) << 16) | __bfloat16_as_ushort(h2);
    uint32_t lA = ((uint32_t)__bfloat16_as_ushort(l1) << 16) | __bfloat16_as_ushort(l0);
    uint32_t lB = ((uint32_t)__bfloat16_as_ushort(l3) << 16) | __bfloat16_as_ushort(l2);
    reinterpret_cast<uint2*>(hi)[i] = make_uint2(hA, hB);
    reinterpret_cast<uint2*>(lo)[i] = make_uint2(lA, lB);
}

// merged converter for 4 segments (keeps pre-GEMM launch count at 3)
__global__ void cvt4_kernel(const float* s0, bf16* h0, bf16* l0, int n0,
                            const float* s1, bf16* h1, bf16* l1, int n1,
                            const float* s2, bf16* h2, bf16* l2, int n2,
                            const float* s3, bf16* h3, bf16* l3, int n3)
{
    int i = blockIdx.x * blockDim.x + threadIdx.x;
    const float* s; bf16 *h, *l; int j = i;
    if (j < n0)      { s = s0; h = h0; l = l0; }
    else { j -= n0;
    if (j < n1)      { s = s1; h = h1; l = l1; }
    else { j -= n1;
    if (j < n2)      { s = s2; h = h2; l = l2; }
    else { j -= n2;
    if (j < n3)      { s = s3; h = h3; l = l3; }
    else return; } } }
    float4 v = reinterpret_cast<const float4*>(s)[j];
    bf16 a0, a1, a2, a3, b0, b1, b2, b3;
    split_bf16(v.x, a0, b0); split_bf16(v.y, a1, b1);
    split_bf16(v.z, a2, b2); split_bf16(v.w, a3, b3);
    uint32_t hA = ((uint32_t)__bfloat16_as_ushort(a1) << 16) | __bfloat16_as_ushort(a0);
    uint32_t hB = ((uint32_t)__bfloat16_as_ushort(a3) << 16) | __bfloat16_as_ushort(a2);
    uint32_t lA = ((uint32_t)__bfloat16_as_ushort(b1) << 16) | __bfloat16_as_ushort(b0);
    uint32_t lB = ((uint32_t)__bfloat16_as_ushort(b3) << 16) | __bfloat16_as_ushort(b2);
    reinterpret_cast<uint2*>(h)[j] = make_uint2(hA, hB);
    reinterpret_cast<uint2*>(l)[j] = make_uint2(lA, lB);
}

// extract dt columns (first 64 of xdbl row) -> bf16 hi/lo [1024 x 64]
__global__ void cvt_xdbl_kernel(const float* __restrict__ xdbl,
                                bf16* __restrict__ hi, bf16* __restrict__ lo)
{
    int i = blockIdx.x * blockDim.x + threadIdx.x;
    int r = i >> 6, c = i & 63;
    float v = xdbl[r * XDBL_W + c];
    bf16 h, l; split_bf16(v, h, l);
    hi[i] = h; lo[i] = l;
}

// ---------------- fused residual-add + LayerNorm (emits bf16 hi/lo) ---------
__global__ void resln_kernel(const float* __restrict__ hin,
                             float* __restrict__ res,
                             bf16* __restrict__ hn_hi, bf16* __restrict__ hn_lo,
                             const float* __restrict__ w,
                             const float* __restrict__ b,
                             int first)
{
    const int l   = blockIdx.x;
    const int tid = threadIdx.x;
    float v[4];
    float s = 0.f, sq = 0.f;
#pragma unroll
    for (int i = 0; i < 4; i++) {
        int c = tid + i * 256;
        float x = hin[l * DMODEL + c];
        if (!first) x += res[l * DMODEL + c];
        res[l * DMODEL + c] = x;
        v[i] = x;
        s  += x;
        sq += x * x;
    }
    __shared__ float shs[8], shq[8];
    const int lane = tid & 31, warp = tid >> 5;
#pragma unroll
    for (int o = 16; o > 0; o >>= 1) {
        s  += __shfl_xor_sync(0xffffffffu, s,  o);
        sq += __shfl_xor_sync(0xffffffffu, sq, o);
    }
    if (lane == 0) { shs[warp] = s; shq[warp] = sq; }
    __syncthreads();
    s = 0.f; sq = 0.f;
#pragma unroll
    for (int i = 0; i < 8; i++) { s += shs[i]; sq += shq[i]; }

    const float inv = 1.f / (float)DMODEL;
    const float mu  = s * inv;
    const float var = sq * inv - mu * mu;
    const float rstd = rsqrtf(var + 1e-5f);
#pragma unroll
    for (int i = 0; i < 4; i++) {
        int c = tid + i * 256;
        float o = (v[i] - mu) * rstd * w[c] + b[c];
        bf16 h, lo; split_bf16(o, h, lo);
        hn_hi[l * DMODEL + c] = h;
        hn_lo[l * DMODEL + c] = lo;
    }
}

// ---------------- causal depthwise conv + SiLU (emits fp32 + bf16 hi/lo) -----
__global__ void conv_silu_kernel(const float* __restrict__ xz,
                                 const float* __restrict__ cw,
                                 const float* __restrict__ cb,
                                 float* __restrict__ xconv,
                                 bf16* __restrict__ xc_hi,
                                 bf16* __restrict__ xc_lo)
{
    const int idx = blockIdx.x * blockDim.x + threadIdx.x;
    if (idx >= L_SEQ * DINNER) return;
    const int l = idx >> 11;
    const int d = idx & (DINNER - 1);

    float acc = cb[d];
    const float w0 = cw[d*4+0], w1 = cw[d*4+1], w2 = cw[d*4+2], w3 = cw[d*4+3];
    if (l >= 3) acc = fmaf(w0, xz[(size_t)(l-3) * (2*DINNER) + d], acc);
    if (l >= 2) acc = fmaf(w1, xz[(size_t)(l-2) * (2*DINNER) + d], acc);
    if (l >= 1) acc = fmaf(w2, xz[(size_t)(l-1) * (2*DINNER) + d], acc);
    acc = fmaf(w3, xz[(size_t)l * (2*DINNER) + d], acc);

    acc = acc / (1.f + expf(-acc));
    xconv[idx] = acc;
    bf16 h, lo; split_bf16(acc, h, lo);
    xc_hi[idx] = h;
    xc_lo[idx] = lo;
}

// ---------------- selective scan + D-skip + SiLU(z) gate (emits y hi/lo) -----
__global__ void scan_kernel(const float* __restrict__ delta,
                            const float* __restrict__ xdbl,
                            const float* __restrict__ xconv,
                            const float* __restrict__ xz,
                            const float* __restrict__ A_log,
                            const float* __restrict__ Dvec,
                            bf16* __restrict__ y_hi,
                            bf16* __restrict__ y_lo)
{
    const int warp = threadIdx.x >> 5;
    const int lane = threadIdx.x & 31;
    const int grp  = lane >> 4;
    const int s    = lane & 15;
    const int d    = blockIdx.x * 16 + warp * 2 + grp;

    const float a2 = -expf(A_log[d * DSTATE + s]) * 1.4426950408889634f;
    const float Dd = Dvec[d];

    float h = 0.f;
#pragma unroll 4
    for (int t = 0; t < L_SEQ; t++) {
        const float dl = delta[(size_t)t * DINNER + d];
        const float xv = xconv[(size_t)t * DINNER + d];
        const float Bs = xdbl[t * XDBL_W + DTRANK + s];
        const float Cs = xdbl[t * XDBL_W + DTRANK + DSTATE + s];

        const float dA = exp2f(dl * a2);
        h = fmaf(dA, h, dl * xv * Bs);

        float acc = h * Cs;
        acc += __shfl_xor_sync(0xffffffffu, acc, 1);
        acc += __shfl_xor_sync(0xffffffffu, acc, 2);
        acc += __shfl_xor_sync(0xffffffffu, acc, 4);
        acc += __shfl_xor_sync(0xffffffffu, acc, 8);

        if (s == 0) {
            const float zv = xz[(size_t)t * (2*DINNER) + DINNER + d];
            float yv = acc + xv * Dd;
            yv *= zv / (1.f + expf(-zv));
            bf16 yh, yl; split_bf16(yv, yh, yl);
            y_hi[(size_t)t * DINNER + d] = yh;
            y_lo[(size_t)t * DINNER + d] = yl;
        }
    }
}

// ---------------- host orchestration ----------------------------------------
extern "C" void kernel_launch(void* const* d_in, const int* in_sizes, int n_in,
                              void* d_out, int out_size)
{
    const float* input   = (const float*)d_in[0];
    const float* input_w = (const float*)d_in[2];
    const float* norm_w  = (const float*)d_in[3];
    const float* norm_b  = (const float*)d_in[4];
    const float* ipw     = (const float*)d_in[5];
    const float* cw      = (const float*)d_in[6];
    const float* cb      = (const float*)d_in[7];
    const float* xpw     = (const float*)d_in[8];
    const float* dtw     = (const float*)d_in[9];
    const float* dtb     = (const float*)d_in[10];
    const float* A_log   = (const float*)d_in[11];
    const float* ssm_D   = (const float*)d_in[12];
    const float* opw     = (const float*)d_in[13];

    float *res, *h, *xz, *xconv, *xdbl, *delta;
    cudaGetSymbolAddress((void**)&res,   g_res);
    cudaGetSymbolAddress((void**)&h,     g_h);
    cudaGetSymbolAddress((void**)&xz,    g_xz);
    cudaGetSymbolAddress((void**)&xconv, g_xconv);
    cudaGetSymbolAddress((void**)&xdbl,  g_xdbl);
    cudaGetSymbolAddress((void**)&delta, g_delta);

    bf16 *in_hi, *in_lo, *inw_hi, *inw_lo, *ipw_hi, *ipw_lo, *xpw_hi, *xpw_lo;
    bf16 *dtw_hi, *dtw_lo, *opw_hi, *opw_lo, *hn_hi, *hn_lo, *xc_hi, *xc_lo;
    bf16 *xd_hi, *xd_lo, *y_hi, *y_lo;
    cudaGetSymbolAddress((void**)&in_hi,  c_in_hi);  cudaGetSymbolAddress((void**)&in_lo,  c_in_lo);
    cudaGetSymbolAddress((void**)&inw_hi, c_inw_hi); cudaGetSymbolAddress((void**)&inw_lo, c_inw_lo);
    cudaGetSymbolAddress((void**)&ipw_hi, c_ipw_hi); cudaGetSymbolAddress((void**)&ipw_lo, c_ipw_lo);
    cudaGetSymbolAddress((void**)&xpw_hi, c_xpw_hi); cudaGetSymbolAddress((void**)&xpw_lo, c_xpw_lo);
    cudaGetSymbolAddress((void**)&dtw_hi, c_dtw_hi); cudaGetSymbolAddress((void**)&dtw_lo, c_dtw_lo);
    cudaGetSymbolAddress((void**)&opw_hi, c_opw_hi); cudaGetSymbolAddress((void**)&opw_lo, c_opw_lo);
    cudaGetSymbolAddress((void**)&hn_hi,  c_hn_hi);  cudaGetSymbolAddress((void**)&hn_lo,  c_hn_lo);
    cudaGetSymbolAddress((void**)&xc_hi,  c_xc_hi);  cudaGetSymbolAddress((void**)&xc_lo,  c_xc_lo);
    cudaGetSymbolAddress((void**)&xd_hi,  c_xd_hi);  cudaGetSymbolAddress((void**)&xd_lo,  c_xd_lo);
    cudaGetSymbolAddress((void**)&y_hi,   c_y_hi);   cudaGetSymbolAddress((void**)&y_lo,   c_y_lo);

    auto g128 = mma_gemm<128, 4, 8>;
    auto g64  = mma_gemm<64, 2, 4>;
    cudaFuncSetAttribute(g128, cudaFuncAttributeMaxDynamicSharedMemorySize, 131072);
    cudaFuncSetAttribute(g64,  cudaFuncAttributeMaxDynamicSharedMemorySize, 98304);

    // ---- launches 0-2: conversions ----
    cvt_kernel<<<(NLAYERS*2*DINNER*DMODEL/4 + 255)/256, 256>>>(
        ipw, ipw_hi, ipw_lo, NLAYERS*2*DINNER*DMODEL/4);                    // #0
    cvt_kernel<<<(NLAYERS*DMODEL*DINNER/4 + 255)/256, 256>>>(
        opw, opw_hi, opw_lo, NLAYERS*DMODEL*DINNER/4);                      // #1
    cvt4_kernel<<<(589824 + 255)/256, 256>>>(                               // #2
        input,   in_hi,  in_lo,  L_SEQ*INLEN/4,
        input_w, inw_hi, inw_lo, DMODEL*INLEN/4,
        xpw,     xpw_hi, xpw_lo, NLAYERS*XDBL_W*DINNER/4,
        dtw,     dtw_hi, dtw_lo, NLAYERS*DINNER*DTRANK/4);

    // #3: h = input @ input_w^T
    g64<<<dim3(DMODEL/128, L_SEQ/64), 256, 98304>>>(
        in_hi, in_lo, INLEN, inw_hi, inw_lo, INLEN, h, DMODEL,
        DMODEL, INLEN, nullptr, 0);

    for (int i = 0; i < NLAYERS; i++) {
        // #4 (layer 0): residual + LN
        resln_kernel<<<L_SEQ, 256>>>(h, res, hn_hi, hn_lo,
                                     norm_w + i*DMODEL, norm_b + i*DMODEL, i == 0);

        // #5 (layer 0): in_proj GEMM  <-- ncu -s 5 -c 1 captures THIS
        g128<<<dim3((2*DINNER)/128, L_SEQ/128), 256, 131072>>>(
            hn_hi, hn_lo, DMODEL,
            ipw_hi + (size_t)i*2*DINNER*DMODEL, ipw_lo + (size_t)i*2*DINNER*DMODEL, DMODEL,
            xz, 2*DINNER, 2*DINNER, DMODEL, nullptr, 0);

        conv_silu_kernel<<<(L_SEQ*DINNER)/256, 256>>>(
            xz, cw + (size_t)i*DINNER*4, cb + i*DINNER, xconv, xc_hi, xc_lo);

        g64<<<dim3(1, L_SEQ/64), 256, 98304>>>(
            xc_hi, xc_lo, DINNER,
            xpw_hi + (size_t)i*XDBL_W*DINNER, xpw_lo + (size_t)i*XDBL_W*DINNER, DINNER,
            xdbl, XDBL_W, XDBL_W, DINNER, nullptr, 0);

        cvt_xdbl_kernel<<<(L_SEQ*DTRANK)/256, 256>>>(xdbl, xd_hi, xd_lo);

        g128<<<dim3(DINNER/128, L_SEQ/128), 256, 131072>>>(
            xd_hi, xd_lo, DTRANK,
            dtw_hi + (size_t)i*DINNER*DTRANK, dtw_lo + (size_t)i*DINNER*DTRANK, DTRANK,
            delta, DINNER, DINNER, DTRANK, dtb + i*DINNER, 1);

        scan_kernel<<<DINNER/16, 256>>>(delta, xdbl, xconv, xz,
                                        A_log + (size_t)i*DINNER*DSTATE,
                                        ssm_D + i*DINNER, y_hi, y_lo);

        float* outp = (i == NLAYERS-1) ? (float*)d_out : h;
        g64<<<dim3(DMODEL/128, L_SEQ/64), 256, 98304>>>(
            y_hi, y_lo, DINNER,
            opw_hi + (size_t)i*DMODEL*DINNER, opw_lo + (size_t)i*DMODEL*DINNER, DINNER,
            outp, DMODEL, DMODEL, DINNER, nullptr, 0);
    }
}

// round 7
// speedup vs baseline: 4.2284x; 2.6266x over previous
#include <cuda_runtime.h>
#include <cuda_bf16.h>
#include <math.h>
#include <stdint.h>

#define L_SEQ   1024
#define INLEN   512
#define DMODEL  1024
#define NLAYERS 4
#define DINNER  2048
#define DSTATE  16
#define DTRANK  64
#define XDBL_W  96   // DT_RANK + 2*D_STATE

typedef __nv_bfloat16 bf16;

// ---------------- fp32 scratch ----------------------------------------------
__device__ float g_res  [L_SEQ * DMODEL];
__device__ float g_h    [L_SEQ * DMODEL];
__device__ float g_xz   [L_SEQ * 2 * DINNER];
__device__ float g_xconv[L_SEQ * DINNER];
__device__ float g_xdbl [L_SEQ * XDBL_W];
__device__ float g_delta[L_SEQ * DINNER];

// ---------------- bf16 hi/lo scratch -----------------------------------------
__device__ bf16 c_in_hi [L_SEQ * INLEN],        c_in_lo [L_SEQ * INLEN];
__device__ bf16 c_inw_hi[DMODEL * INLEN],       c_inw_lo[DMODEL * INLEN];
__device__ bf16 c_ipw_hi[NLAYERS * 2*DINNER * DMODEL], c_ipw_lo[NLAYERS * 2*DINNER * DMODEL];
__device__ bf16 c_xpw_hi[NLAYERS * XDBL_W * DINNER],   c_xpw_lo[NLAYERS * XDBL_W * DINNER];
__device__ bf16 c_dtw_hi[NLAYERS * DINNER * DTRANK],   c_dtw_lo[NLAYERS * DINNER * DTRANK];
__device__ bf16 c_opw_hi[NLAYERS * DMODEL * DINNER],   c_opw_lo[NLAYERS * DMODEL * DINNER];
__device__ bf16 c_hn_hi [L_SEQ * DMODEL],       c_hn_lo [L_SEQ * DMODEL];
__device__ bf16 c_xc_hi [L_SEQ * DINNER],       c_xc_lo [L_SEQ * DINNER];
__device__ bf16 c_xd_hi [L_SEQ * DTRANK],       c_xd_lo [L_SEQ * DTRANK];
__device__ bf16 c_y_hi  [L_SEQ * DINNER],       c_y_lo  [L_SEQ * DINNER];

// ============================ PTX helpers ====================================
__device__ __forceinline__ uint32_t smem_u32(const void* p) {
    uint32_t a;
    asm("{ .reg .u64 t; cvta.to.shared.u64 t, %1; cvt.u32.u64 %0, t; }"
        : "=r"(a) : "l"(p));
    return a;
}
#define CP_ASYNC16(dst, src, sz) \
    asm volatile("cp.async.cg.shared.global [%0], [%1], 16, %2;" \
                 :: "r"(dst), "l"(src), "r"(sz))
#define CP_COMMIT() asm volatile("cp.async.commit_group;" ::: "memory")
#define CP_WAIT0()  asm volatile("cp.async.wait_group 0;" ::: "memory")
#define CP_WAIT1()  asm volatile("cp.async.wait_group 1;" ::: "memory")

#define LDM4(r0, r1, r2, r3, addr) \
    asm volatile("ldmatrix.sync.aligned.m8n8.x4.shared.b16 {%0,%1,%2,%3}, [%4];" \
                 : "=r"(r0), "=r"(r1), "=r"(r2), "=r"(r3) : "r"(addr))

#define MMA_BF16(c, a, b)                                                      \
    asm volatile(                                                              \
        "mma.sync.aligned.m16n8k16.row.col.f32.bf16.bf16.f32 "                 \
        "{%0,%1,%2,%3}, {%4,%5,%6,%7}, {%8,%9}, {%0,%1,%2,%3};"                \
        : "+f"((c)[0]), "+f"((c)[1]), "+f"((c)[2]), "+f"((c)[3])               \
        : "r"((a)[0]), "r"((a)[1]), "r"((a)[2]), "r"((a)[3]),                  \
          "r"((b)[0]), "r"((b)[1]))

__device__ __forceinline__ uint32_t swz(uint32_t off) {
    return off ^ ((off >> 3) & 0x70);
}
__device__ __forceinline__ void split_bf16(float v, bf16& hi, bf16& lo) {
    hi = __float2bfloat16(v);
    lo = __float2bfloat16(v - __bfloat162float(hi));
}

// =============================================================================
// bf16 hi/lo split-precision NT GEMM (3 MMAs per k16), 3-stage cp.async.
//   C[m,n] = sum_k A[m,k]*B[n,k]
//   Ksplit = K per CTA along z (split-K); gridDim.z * Ksplit = K total.
//   mode 0: plain store; mode 1: softplus(acc+bias); mode 2: atomicAdd.
// =============================================================================
template<int BM, int WMW, int NT>
__global__ void __launch_bounds__(256, 1)
mma_gemm(const bf16* __restrict__ Ahi, const bf16* __restrict__ Alo, int lda,
         const bf16* __restrict__ Bhi, const bf16* __restrict__ Blo, int ldb,
         float* __restrict__ C, int ldc,
         int Nvalid, int Ksplit,
         const float* __restrict__ bias, int mode)
{
    constexpr int ABYTES = BM * 128;
    constexpr int BBYTES = 128 * 128;
    constexpr int STAGE  = 2 * ABYTES + 2 * BBYTES;
    constexpr int A_ITER = (BM * 8) / 256;
    constexpr int B_ITER = 4;

    extern __shared__ char smem[];
    const uint32_t sb = smem_u32(smem);

    const int tid  = threadIdx.x;
    const int wid  = tid >> 5;
    const int lane = tid & 31;
    const int m0   = blockIdx.y * BM;
    const int n0   = blockIdx.x * 128;
    const int kbase = blockIdx.z * Ksplit;

    const int warp_m = (wid % WMW) * 32;
    const int warp_n = (wid / WMW) * (NT * 8);

    float acc[2][NT][4];
#pragma unroll
    for (int mt = 0; mt < 2; mt++)
#pragma unroll
        for (int nt = 0; nt < NT; nt++)
#pragma unroll
            for (int i = 0; i < 4; i++) acc[mt][nt][i] = 0.f;

    auto stage_load = [&](int c, int buf) {
        const int k0 = kbase + (c << 6);
        const uint32_t st = sb + buf * STAGE;
#pragma unroll
        for (int i = 0; i < A_ITER; i++) {
            int j = tid + i * 256;
            int r = j >> 3, u = j & 7;
            uint32_t so = swz((uint32_t)(r * 128 + u * 16));
            const char* ga = (const char*)(Ahi + (size_t)(m0 + r) * lda + k0 + u * 8);
            const char* gl = (const char*)(Alo + (size_t)(m0 + r) * lda + k0 + u * 8);
            CP_ASYNC16(st + so, ga, 16);
            CP_ASYNC16(st + ABYTES + so, gl, 16);
        }
#pragma unroll
        for (int i = 0; i < B_ITER; i++) {
            int j = tid + i * 256;
            int r = j >> 3, u = j & 7;
            int gn = n0 + r;
            int sz = (gn < Nvalid) ? 16 : 0;
            int gc = (gn < Nvalid) ? gn : 0;
            uint32_t so = swz((uint32_t)(r * 128 + u * 16));
            const char* gb = (const char*)(Bhi + (size_t)gc * ldb + k0 + u * 8);
            const char* gl = (const char*)(Blo + (size_t)gc * ldb + k0 + u * 8);
            CP_ASYNC16(st + 2 * ABYTES + so, gb, sz);
            CP_ASYNC16(st + 2 * ABYTES + BBYTES + so, gl, sz);
        }
        CP_COMMIT();
    };

    auto mma_chunk = [&](int buf) {
        const uint32_t st  = sb + buf * STAGE;
        const uint32_t sAh = st;
        const uint32_t sAl = st + ABYTES;
        const uint32_t sBh = st + 2 * ABYTES;
        const uint32_t sBl = sBh + BBYTES;
#pragma unroll
        for (int ks = 0; ks < 4; ks++) {
            const int kb = ks * 32;
            uint32_t bh[NT][2], bl[NT][2];
#pragma unroll
            for (int p = 0; p < NT / 2; p++) {
                int row = warp_n + p * 16 + ((lane >> 4) << 3) + (lane & 7);
                int kbyte = kb + ((lane >> 3) & 1) * 16;
                uint32_t off = swz((uint32_t)(row * 128 + kbyte));
                LDM4(bh[2*p][0], bh[2*p][1], bh[2*p+1][0], bh[2*p+1][1], sBh + off);
                LDM4(bl[2*p][0], bl[2*p][1], bl[2*p+1][0], bl[2*p+1][1], sBl + off);
            }
#pragma unroll
            for (int mt = 0; mt < 2; mt++) {
                int row = warp_m + mt * 16 + (lane & 15);
                int kbyte = kb + (lane >> 4) * 16;
                uint32_t off = swz((uint32_t)(row * 128 + kbyte));
                uint32_t ah[4], al[4];
                LDM4(ah[0], ah[1], ah[2], ah[3], sAh + off);
                LDM4(al[0], al[1], al[2], al[3], sAl + off);
#pragma unroll
                for (int nt = 0; nt < NT; nt++) MMA_BF16(acc[mt][nt], ah, bh[nt]);
#pragma unroll
                for (int nt = 0; nt < NT; nt++) MMA_BF16(acc[mt][nt], ah, bl[nt]);
#pragma unroll
                for (int nt = 0; nt < NT; nt++) MMA_BF16(acc[mt][nt], al, bh[nt]);
            }
        }
    };

    // ---- 3-stage pipeline: 2 chunks always in flight ----
    const int NC = Ksplit >> 6;
    stage_load(0, 0);
    if (NC > 1) stage_load(1, 1);
    for (int c = 0; c < NC; c++) {
        if (c + 1 < NC) { CP_WAIT1(); } else { CP_WAIT0(); }
        __syncthreads();
        if (c + 2 < NC) stage_load(c + 2, (c + 2) % 3);
        mma_chunk(c % 3);
    }

    // ---- epilogue ----
    const int qrow = lane >> 2;
    const int qcol = (lane & 3) * 2;
#pragma unroll
    for (int mt = 0; mt < 2; mt++) {
        int row0 = m0 + warp_m + mt * 16 + qrow;
        int row1 = row0 + 8;
#pragma unroll
        for (int nt = 0; nt < NT; nt++) {
            int gn = n0 + warp_n + nt * 8 + qcol;
            if (gn >= Nvalid) continue;
            float2 v0 = make_float2(acc[mt][nt][0], acc[mt][nt][1]);
            float2 v1 = make_float2(acc[mt][nt][2], acc[mt][nt][3]);
            if (mode == 1) {
                float b0 = bias[gn], b1 = bias[gn + 1];
                v0.x += b0; v0.y += b1; v1.x += b0; v1.y += b1;
                v0.x = (v0.x > 20.f) ? v0.x : log1pf(expf(v0.x));
                v0.y = (v0.y > 20.f) ? v0.y : log1pf(expf(v0.y));
                v1.x = (v1.x > 20.f) ? v1.x : log1pf(expf(v1.x));
                v1.y = (v1.y > 20.f) ? v1.y : log1pf(expf(v1.y));
            }
            if (mode == 2) {
                atomicAdd(&C[(size_t)row0 * ldc + gn],     v0.x);
                atomicAdd(&C[(size_t)row0 * ldc + gn + 1], v0.y);
                atomicAdd(&C[(size_t)row1 * ldc + gn],     v1.x);
                atomicAdd(&C[(size_t)row1 * ldc + gn + 1], v1.y);
            } else {
                *reinterpret_cast<float2*>(C + (size_t)row0 * ldc + gn) = v0;
                *reinterpret_cast<float2*>(C + (size_t)row1 * ldc + gn) = v1;
            }
        }
    }
}

// ---------------- fp32 -> bf16 hi/lo converters -------------------------------
__global__ void cvt_kernel(const float* __restrict__ src,
                           bf16* __restrict__ hi, bf16* __restrict__ lo, int n4)
{
    int i = blockIdx.x * blockDim.x + threadIdx.x;
    if (i >= n4) return;
    float4 v = reinterpret_cast<const float4*>(src)[i];
    bf16 h0, h1, h2, h3, l0, l1, l2, l3;
    split_bf16(v.x, h0, l0); split_bf16(v.y, h1, l1);
    split_bf16(v.z, h2, l2); split_bf16(v.w, h3, l3);
    uint32_t hA = ((uint32_t)__bfloat16_as_ushort(h1) << 16) | __bfloat16_as_ushort(h0);
    uint32_t hB = ((uint32_t)__bfloat16_as_ushort(h3) << 16) | __bfloat16_as_ushort(h2);
    uint32_t lA = ((uint32_t)__bfloat16_as_ushort(l1) << 16) | __bfloat16_as_ushort(l0);
    uint32_t lB = ((uint32_t)__bfloat16_as_ushort(l3) << 16) | __bfloat16_as_ushort(l2);
    reinterpret_cast<uint2*>(hi)[i] = make_uint2(hA, hB);
    reinterpret_cast<uint2*>(lo)[i] = make_uint2(lA, lB);
}

__global__ void cvt4_kernel(const float* s0, bf16* h0, bf16* l0, int n0,
                            const float* s1, bf16* h1, bf16* l1, int n1,
                            const float* s2, bf16* h2, bf16* l2, int n2,
                            const float* s3, bf16* h3, bf16* l3, int n3)
{
    int i = blockIdx.x * blockDim.x + threadIdx.x;
    const float* s; bf16 *h, *l; int j = i;
    if (j < n0)      { s = s0; h = h0; l = l0; }
    else { j -= n0;
    if (j < n1)      { s = s1; h = h1; l = l1; }
    else { j -= n1;
    if (j < n2)      { s = s2; h = h2; l = l2; }
    else { j -= n2;
    if (j < n3)      { s = s3; h = h3; l = l3; }
    else return; } } }
    float4 v = reinterpret_cast<const float4*>(s)[j];
    bf16 a0, a1, a2, a3, b0, b1, b2, b3;
    split_bf16(v.x, a0, b0); split_bf16(v.y, a1, b1);
    split_bf16(v.z, a2, b2); split_bf16(v.w, a3, b3);
    uint32_t hA = ((uint32_t)__bfloat16_as_ushort(a1) << 16) | __bfloat16_as_ushort(a0);
    uint32_t hB = ((uint32_t)__bfloat16_as_ushort(a3) << 16) | __bfloat16_as_ushort(a2);
    uint32_t lA = ((uint32_t)__bfloat16_as_ushort(b1) << 16) | __bfloat16_as_ushort(b0);
    uint32_t lB = ((uint32_t)__bfloat16_as_ushort(b3) << 16) | __bfloat16_as_ushort(b2);
    reinterpret_cast<uint2*>(h)[j] = make_uint2(hA, hB);
    reinterpret_cast<uint2*>(l)[j] = make_uint2(lA, lB);
}

__global__ void cvt_xdbl_kernel(const float* __restrict__ xdbl,
                                bf16* __restrict__ hi, bf16* __restrict__ lo)
{
    int i = blockIdx.x * blockDim.x + threadIdx.x;
    int r = i >> 6, c = i & 63;
    float v = xdbl[r * XDBL_W + c];
    bf16 h, l; split_bf16(v, h, l);
    hi[i] = h; lo[i] = l;
}

// ---------------- fused residual-add + LayerNorm ------------------------------
__global__ void resln_kernel(const float* __restrict__ hin,
                             float* __restrict__ res,
                             bf16* __restrict__ hn_hi, bf16* __restrict__ hn_lo,
                             const float* __restrict__ w,
                             const float* __restrict__ b,
                             int first)
{
    const int l   = blockIdx.x;
    const int tid = threadIdx.x;
    float v[4];
    float s = 0.f, sq = 0.f;
#pragma unroll
    for (int i = 0; i < 4; i++) {
        int c = tid + i * 256;
        float x = hin[l * DMODEL + c];
        if (!first) x += res[l * DMODEL + c];
        res[l * DMODEL + c] = x;
        v[i] = x;
        s  += x;
        sq += x * x;
    }
    __shared__ float shs[8], shq[8];
    const int lane = tid & 31, warp = tid >> 5;
#pragma unroll
    for (int o = 16; o > 0; o >>= 1) {
        s  += __shfl_xor_sync(0xffffffffu, s,  o);
        sq += __shfl_xor_sync(0xffffffffu, sq, o);
    }
    if (lane == 0) { shs[warp] = s; shq[warp] = sq; }
    __syncthreads();
    s = 0.f; sq = 0.f;
#pragma unroll
    for (int i = 0; i < 8; i++) { s += shs[i]; sq += shq[i]; }

    const float inv = 1.f / (float)DMODEL;
    const float mu  = s * inv;
    const float var = sq * inv - mu * mu;
    const float rstd = rsqrtf(var + 1e-5f);
#pragma unroll
    for (int i = 0; i < 4; i++) {
        int c = tid + i * 256;
        float o = (v[i] - mu) * rstd * w[c] + b[c];
        bf16 h, lo; split_bf16(o, h, lo);
        hn_hi[l * DMODEL + c] = h;
        hn_lo[l * DMODEL + c] = lo;
    }
}

// ---------------- conv + SiLU; also zeroes xdbl for split-K atomics ----------
__global__ void conv_silu_kernel(const float* __restrict__ xz,
                                 const float* __restrict__ cw,
                                 const float* __restrict__ cb,
                                 float* __restrict__ xconv,
                                 bf16* __restrict__ xc_hi,
                                 bf16* __restrict__ xc_lo,
                                 float* __restrict__ xdbl_zero)
{
    const int idx = blockIdx.x * blockDim.x + threadIdx.x;
    if (idx >= L_SEQ * DINNER) return;
    const int l = idx >> 11;
    const int d = idx & (DINNER - 1);

    float acc = cb[d];
    const float w0 = cw[d*4+0], w1 = cw[d*4+1], w2 = cw[d*4+2], w3 = cw[d*4+3];
    if (l >= 3) acc = fmaf(w0, xz[(size_t)(l-3) * (2*DINNER) + d], acc);
    if (l >= 2) acc = fmaf(w1, xz[(size_t)(l-2) * (2*DINNER) + d], acc);
    if (l >= 1) acc = fmaf(w2, xz[(size_t)(l-1) * (2*DINNER) + d], acc);
    acc = fmaf(w3, xz[(size_t)l * (2*DINNER) + d], acc);

    acc = acc / (1.f + expf(-acc));
    xconv[idx] = acc;
    bf16 h, lo; split_bf16(acc, h, lo);
    xc_hi[idx] = h;
    xc_lo[idx] = lo;

    if (idx < L_SEQ * XDBL_W) xdbl_zero[idx] = 0.f;
}

// =============================================================================
// Chunked parallel selective scan.
// One CTA per channel d. 256 threads = 16 time-chunks (j) x 16 states (s).
// Phase 1: per-(j,s) scan of 64 steps -> (P = prod dA, S = local state end).
// Combine: serial 16-step prefix over chunks (per s).
// Phase 2: rescan with corrected h0; y_t = sum_s h_t[s] * C_t[s]  (+ skip, gate)
// =============================================================================
__global__ void __launch_bounds__(256, 4)
scan_kernel(const float* __restrict__ delta,
            const float* __restrict__ xdbl,
            const float* __restrict__ xconv,
            const float* __restrict__ xz,
            const float* __restrict__ A_log,
            const float* __restrict__ Dvec,
            bf16* __restrict__ y_hi,
            bf16* __restrict__ y_lo)
{
    const int d    = blockIdx.x;
    const int lane = threadIdx.x & 31;
    const int wrp  = threadIdx.x >> 5;
    const int j    = wrp * 2 + (lane >> 4);   // time chunk 0..15
    const int s    = lane & 15;               // state 0..15
    const int t0   = j * 64;

    const float a2 = -expf(A_log[d * DSTATE + s]) * 1.4426950408889634f;

    __shared__ float shP[16][16];
    __shared__ float shS[16][16];

    // ---- phase 1: local chunk scan ----
    float P = 1.f, S = 0.f;
#pragma unroll 4
    for (int k = 0; k < 64; k++) {
        const int t = t0 + k;
        const float dl = delta[(size_t)t * DINNER + d];
        const float xv = xconv[(size_t)t * DINNER + d];
        const float Bs = xdbl[t * XDBL_W + DTRANK + s];
        const float dA = exp2f(dl * a2);
        P *= dA;
        S = fmaf(dA, S, dl * xv * Bs);
    }
    shP[j][s] = P;
    shS[j][s] = S;
    __syncthreads();

    // ---- combine: serial prefix over 16 chunks, one thread per state ----
    if (threadIdx.x < 16) {
        const int ss = threadIdx.x;
        float run = shS[0][ss];
#pragma unroll
        for (int jj = 1; jj < 16; jj++) {
            run = fmaf(shP[jj][ss], run, shS[jj][ss]);
            shS[jj][ss] = run;      // shS[jj] = h at END of chunk jj
        }
    }
    __syncthreads();

    // ---- phase 2: rescan with corrected h0, produce y ----
    float h = (j == 0) ? 0.f : shS[j - 1][s];
    const float Dd = Dvec[d];
#pragma unroll 4
    for (int k = 0; k < 64; k++) {
        const int t = t0 + k;
        const float dl = delta[(size_t)t * DINNER + d];
        const float xv = xconv[(size_t)t * DINNER + d];
        const float Bs = xdbl[t * XDBL_W + DTRANK + s];
        const float Cs = xdbl[t * XDBL_W + DTRANK + DSTATE + s];
        const float dA = exp2f(dl * a2);
        h = fmaf(dA, h, dl * xv * Bs);

        float acc = h * Cs;
        acc += __shfl_xor_sync(0xffffffffu, acc, 1);
        acc += __shfl_xor_sync(0xffffffffu, acc, 2);
        acc += __shfl_xor_sync(0xffffffffu, acc, 4);
        acc += __shfl_xor_sync(0xffffffffu, acc, 8);

        if (s == 0) {
            const float zv = xz[(size_t)t * (2*DINNER) + DINNER + d];
            float yv = acc + xv * Dd;
            yv *= zv / (1.f + expf(-zv));
            bf16 yh, yl; split_bf16(yv, yh, yl);
            y_hi[(size_t)t * DINNER + d] = yh;
            y_lo[(size_t)t * DINNER + d] = yl;
        }
    }
}

// ---------------- host orchestration ----------------------------------------
extern "C" void kernel_launch(void* const* d_in, const int* in_sizes, int n_in,
                              void* d_out, int out_size)
{
    const float* input   = (const float*)d_in[0];
    const float* input_w = (const float*)d_in[2];
    const float* norm_w  = (const float*)d_in[3];
    const float* norm_b  = (const float*)d_in[4];
    const float* ipw     = (const float*)d_in[5];
    const float* cw      = (const float*)d_in[6];
    const float* cb      = (const float*)d_in[7];
    const float* xpw     = (const float*)d_in[8];
    const float* dtw     = (const float*)d_in[9];
    const float* dtb     = (const float*)d_in[10];
    const float* A_log   = (const float*)d_in[11];
    const float* ssm_D   = (const float*)d_in[12];
    const float* opw     = (const float*)d_in[13];

    float *res, *h, *xz, *xconv, *xdbl, *delta;
    cudaGetSymbolAddress((void**)&res,   g_res);
    cudaGetSymbolAddress((void**)&h,     g_h);
    cudaGetSymbolAddress((void**)&xz,    g_xz);
    cudaGetSymbolAddress((void**)&xconv, g_xconv);
    cudaGetSymbolAddress((void**)&xdbl,  g_xdbl);
    cudaGetSymbolAddress((void**)&delta, g_delta);

    bf16 *in_hi, *in_lo, *inw_hi, *inw_lo, *ipw_hi, *ipw_lo, *xpw_hi, *xpw_lo;
    bf16 *dtw_hi, *dtw_lo, *opw_hi, *opw_lo, *hn_hi, *hn_lo, *xc_hi, *xc_lo;
    bf16 *xd_hi, *xd_lo, *y_hi, *y_lo;
    cudaGetSymbolAddress((void**)&in_hi,  c_in_hi);  cudaGetSymbolAddress((void**)&in_lo,  c_in_lo);
    cudaGetSymbolAddress((void**)&inw_hi, c_inw_hi); cudaGetSymbolAddress((void**)&inw_lo, c_inw_lo);
    cudaGetSymbolAddress((void**)&ipw_hi, c_ipw_hi); cudaGetSymbolAddress((void**)&ipw_lo, c_ipw_lo);
    cudaGetSymbolAddress((void**)&xpw_hi, c_xpw_hi); cudaGetSymbolAddress((void**)&xpw_lo, c_xpw_lo);
    cudaGetSymbolAddress((void**)&dtw_hi, c_dtw_hi); cudaGetSymbolAddress((void**)&dtw_lo, c_dtw_lo);
    cudaGetSymbolAddress((void**)&opw_hi, c_opw_hi); cudaGetSymbolAddress((void**)&opw_lo, c_opw_lo);
    cudaGetSymbolAddress((void**)&hn_hi,  c_hn_hi);  cudaGetSymbolAddress((void**)&hn_lo,  c_hn_lo);
    cudaGetSymbolAddress((void**)&xc_hi,  c_xc_hi);  cudaGetSymbolAddress((void**)&xc_lo,  c_xc_lo);
    cudaGetSymbolAddress((void**)&xd_hi,  c_xd_hi);  cudaGetSymbolAddress((void**)&xd_lo,  c_xd_lo);
    cudaGetSymbolAddress((void**)&y_hi,   c_y_hi);   cudaGetSymbolAddress((void**)&y_lo,   c_y_lo);

    auto g128 = mma_gemm<128, 4, 8>;
    auto g64  = mma_gemm<64, 2, 4>;
    cudaFuncSetAttribute(g128, cudaFuncAttributeMaxDynamicSharedMemorySize, 196608);
    cudaFuncSetAttribute(g64,  cudaFuncAttributeMaxDynamicSharedMemorySize, 147456);

    // conversions
    cvt_kernel<<<(NLAYERS*2*DINNER*DMODEL/4 + 255)/256, 256>>>(
        ipw, ipw_hi, ipw_lo, NLAYERS*2*DINNER*DMODEL/4);
    cvt_kernel<<<(NLAYERS*DMODEL*DINNER/4 + 255)/256, 256>>>(
        opw, opw_hi, opw_lo, NLAYERS*DMODEL*DINNER/4);
    cvt4_kernel<<<(589824 + 255)/256, 256>>>(
        input,   in_hi,  in_lo,  L_SEQ*INLEN/4,
        input_w, inw_hi, inw_lo, DMODEL*INLEN/4,
        xpw,     xpw_hi, xpw_lo, NLAYERS*XDBL_W*DINNER/4,
        dtw,     dtw_hi, dtw_lo, NLAYERS*DINNER*DTRANK/4);

    // h = input @ input_w^T
    g64<<<dim3(DMODEL/128, L_SEQ/64), 256, 147456>>>(
        in_hi, in_lo, INLEN, inw_hi, inw_lo, INLEN, h, DMODEL,
        DMODEL, INLEN, nullptr, 0);

    for (int i = 0; i < NLAYERS; i++) {
        resln_kernel<<<L_SEQ, 256>>>(h, res, hn_hi, hn_lo,
                                     norm_w + i*DMODEL, norm_b + i*DMODEL, i == 0);

        // xz = hn @ in_proj_w^T
        g128<<<dim3((2*DINNER)/128, L_SEQ/128), 256, 196608>>>(
            hn_hi, hn_lo, DMODEL,
            ipw_hi + (size_t)i*2*DINNER*DMODEL, ipw_lo + (size_t)i*2*DINNER*DMODEL, DMODEL,
            xz, 2*DINNER, 2*DINNER, DMODEL, nullptr, 0);

        conv_silu_kernel<<<(L_SEQ*DINNER)/256, 256>>>(
            xz, cw + (size_t)i*DINNER*4, cb + i*DINNER, xconv, xc_hi, xc_lo, xdbl);

        // x_dbl = xconv @ x_proj_w^T   split-K=8 -> 128 CTAs, atomic epilogue
        g64<<<dim3(1, L_SEQ/64, 8), 256, 147456>>>(
            xc_hi, xc_lo, DINNER,
            xpw_hi + (size_t)i*XDBL_W*DINNER, xpw_lo + (size_t)i*XDBL_W*DINNER, DINNER,
            xdbl, XDBL_W, XDBL_W, DINNER/8, nullptr, 2);

        cvt_xdbl_kernel<<<(L_SEQ*DTRANK)/256, 256>>>(xdbl, xd_hi, xd_lo);

        // delta = softplus(xd @ dt_proj_w^T + bias)
        g128<<<dim3(DINNER/128, L_SEQ/128), 256, 196608>>>(
            xd_hi, xd_lo, DTRANK,
            dtw_hi + (size_t)i*DINNER*DTRANK, dtw_lo + (size_t)i*DINNER*DTRANK, DTRANK,
            delta, DINNER, DINNER, DTRANK, dtb + i*DINNER, 1);

        // chunked parallel scan (2048 CTAs)
        scan_kernel<<<DINNER, 256>>>(delta, xdbl, xconv, xz,
                                     A_log + (size_t)i*DINNER*DSTATE,
                                     ssm_D + i*DINNER, y_hi, y_lo);

        float* outp = (i == NLAYERS-1) ? (float*)d_out : h;
        g64<<<dim3(DMODEL/128, L_SEQ/64), 256, 147456>>>(
            y_hi, y_lo, DINNER,
            opw_hi + (size_t)i*DMODEL*DINNER, opw_lo + (size_t)i*DMODEL*DINNER, DINNER,
            outp, DMODEL, DMODEL, DINNER, nullptr, 0);
    }
}

// round 8
// speedup vs baseline: 5.4006x; 1.2772x over previous
#include <cuda_runtime.h>
#include <cuda_bf16.h>
#include <math.h>
#include <stdint.h>

#define L_SEQ   1024
#define INLEN   512
#define DMODEL  1024
#define NLAYERS 4
#define DINNER  2048
#define DSTATE  16
#define DTRANK  64
#define XDBL_W  96   // DT_RANK + 2*D_STATE

typedef __nv_bfloat16 bf16;

// ---------------- fp32 scratch ----------------------------------------------
__device__ float g_res   [L_SEQ * DMODEL];
__device__ float g_h     [L_SEQ * DMODEL];
__device__ float g_xz    [L_SEQ * 2 * DINNER];
__device__ float g_xconv [L_SEQ * DINNER];
__device__ float g_xdbl  [L_SEQ * XDBL_W];
__device__ float g_delta [L_SEQ * DINNER];
__device__ float g_deltaT[DINNER * L_SEQ];
__device__ float g_xcT   [DINNER * L_SEQ];
__device__ float g_zT    [DINNER * L_SEQ];
__device__ float g_yT    [DINNER * L_SEQ];

// ---------------- bf16 hi/lo scratch -----------------------------------------
__device__ bf16 c_in_hi [L_SEQ * INLEN],        c_in_lo [L_SEQ * INLEN];
__device__ bf16 c_inw_hi[DMODEL * INLEN],       c_inw_lo[DMODEL * INLEN];
__device__ bf16 c_ipw_hi[NLAYERS * 2*DINNER * DMODEL], c_ipw_lo[NLAYERS * 2*DINNER * DMODEL];
__device__ bf16 c_xpw_hi[NLAYERS * XDBL_W * DINNER],   c_xpw_lo[NLAYERS * XDBL_W * DINNER];
__device__ bf16 c_dtw_hi[NLAYERS * DINNER * DTRANK],   c_dtw_lo[NLAYERS * DINNER * DTRANK];
__device__ bf16 c_opw_hi[NLAYERS * DMODEL * DINNER],   c_opw_lo[NLAYERS * DMODEL * DINNER];
__device__ bf16 c_hn_hi [L_SEQ * DMODEL],       c_hn_lo [L_SEQ * DMODEL];
__device__ bf16 c_xc_hi [L_SEQ * DINNER],       c_xc_lo [L_SEQ * DINNER];
__device__ bf16 c_xd_hi [L_SEQ * DTRANK],       c_xd_lo [L_SEQ * DTRANK];
__device__ bf16 c_y_hi  [L_SEQ * DINNER],       c_y_lo  [L_SEQ * DINNER];

// ============================ PTX helpers ====================================
__device__ __forceinline__ uint32_t smem_u32(const void* p) {
    uint32_t a;
    asm("{ .reg .u64 t; cvta.to.shared.u64 t, %1; cvt.u32.u64 %0, t; }"
        : "=r"(a) : "l"(p));
    return a;
}
#define CP_ASYNC16(dst, src, sz) \
    asm volatile("cp.async.cg.shared.global [%0], [%1], 16, %2;" \
                 :: "r"(dst), "l"(src), "r"(sz))
#define CP_COMMIT() asm volatile("cp.async.commit_group;" ::: "memory")
#define CP_WAIT0()  asm volatile("cp.async.wait_group 0;" ::: "memory")

#define LDM4(r0, r1, r2, r3, addr) \
    asm volatile("ldmatrix.sync.aligned.m8n8.x4.shared.b16 {%0,%1,%2,%3}, [%4];" \
                 : "=r"(r0), "=r"(r1), "=r"(r2), "=r"(r3) : "r"(addr))

#define MMA_BF16(c, a, b)                                                      \
    asm volatile(                                                              \
        "mma.sync.aligned.m16n8k16.row.col.f32.bf16.bf16.f32 "                 \
        "{%0,%1,%2,%3}, {%4,%5,%6,%7}, {%8,%9}, {%0,%1,%2,%3};"                \
        : "+f"((c)[0]), "+f"((c)[1]), "+f"((c)[2]), "+f"((c)[3])               \
        : "r"((a)[0]), "r"((a)[1]), "r"((a)[2]), "r"((a)[3]),                  \
          "r"((b)[0]), "r"((b)[1]))

__device__ __forceinline__ uint32_t swz(uint32_t off) {
    return off ^ ((off >> 3) & 0x70);
}
__device__ __forceinline__ void split_bf16(float v, bf16& hi, bf16& lo) {
    hi = __float2bfloat16(v);
    lo = __float2bfloat16(v - __bfloat162float(hi));
}

// =============================================================================
// bf16 hi/lo split NT GEMM (3 MMAs per k16), 64x128 tile, 2-stage cp.async,
// 2 CTAs/SM.  C[m,n] = sum_k A[m,k]*B[n,k]
//   Ksplit = K per z-slice.  mode 0: store; 1: softplus(acc+bias); 2: atomicAdd
// =============================================================================
#define G_ABYTES 8192                    // 64 rows x 64 bf16 x 2B
#define G_BBYTES 16384                   // 128 rows x 64 bf16 x 2B
#define G_STAGE  (2*G_ABYTES + 2*G_BBYTES)   // 48 KB
#define G_SMEM   (2 * G_STAGE)               // 96 KB

__global__ void __launch_bounds__(256, 2)
mma_gemm(const bf16* __restrict__ Ahi, const bf16* __restrict__ Alo, int lda,
         const bf16* __restrict__ Bhi, const bf16* __restrict__ Blo, int ldb,
         float* __restrict__ C, int ldc,
         int Nvalid, int Ksplit,
         const float* __restrict__ bias, int mode)
{
    extern __shared__ char smem[];
    const uint32_t sb = smem_u32(smem);

    const int tid  = threadIdx.x;
    const int wid  = tid >> 5;
    const int lane = tid & 31;
    const int m0   = blockIdx.y * 64;
    const int n0   = blockIdx.x * 128;
    const int kbase = blockIdx.z * Ksplit;

    const int warp_m = (wid & 1) * 32;        // 2 warps along M
    const int warp_n = (wid >> 1) * 32;       // 4 warps along N (4 nt x 8)

    float acc[2][4][4];
#pragma unroll
    for (int mt = 0; mt < 2; mt++)
#pragma unroll
        for (int nt = 0; nt < 4; nt++)
#pragma unroll
            for (int i = 0; i < 4; i++) acc[mt][nt][i] = 0.f;

    auto stage_load = [&](int c, int buf) {
        const int k0 = kbase + (c << 6);
        const uint32_t st = sb + buf * G_STAGE;
#pragma unroll
        for (int i = 0; i < 2; i++) {            // A: 64 rows x 8 u16-units
            int j = tid + i * 256;
            int r = j >> 3, u = j & 7;
            uint32_t so = swz((uint32_t)(r * 128 + u * 16));
            const char* ga = (const char*)(Ahi + (size_t)(m0 + r) * lda + k0 + u * 8);
            const char* gl = (const char*)(Alo + (size_t)(m0 + r) * lda + k0 + u * 8);
            CP_ASYNC16(st + so, ga, 16);
            CP_ASYNC16(st + G_ABYTES + so, gl, 16);
        }
#pragma unroll
        for (int i = 0; i < 4; i++) {            // B: 128 rows
            int j = tid + i * 256;
            int r = j >> 3, u = j & 7;
            int gn = n0 + r;
            int sz = (gn < Nvalid) ? 16 : 0;
            int gc = (gn < Nvalid) ? gn : 0;
            uint32_t so = swz((uint32_t)(r * 128 + u * 16));
            const char* gb = (const char*)(Bhi + (size_t)gc * ldb + k0 + u * 8);
            const char* gl = (const char*)(Blo + (size_t)gc * ldb + k0 + u * 8);
            CP_ASYNC16(st + 2 * G_ABYTES + so, gb, sz);
            CP_ASYNC16(st + 2 * G_ABYTES + G_BBYTES + so, gl, sz);
        }
        CP_COMMIT();
    };

    auto mma_chunk = [&](int buf) {
        const uint32_t st  = sb + buf * G_STAGE;
        const uint32_t sAh = st;
        const uint32_t sAl = st + G_ABYTES;
        const uint32_t sBh = st + 2 * G_ABYTES;
        const uint32_t sBl = sBh + G_BBYTES;
#pragma unroll
        for (int ks = 0; ks < 4; ks++) {
            const int kb = ks * 32;
            uint32_t bh[4][2], bl[4][2];
#pragma unroll
            for (int p = 0; p < 2; p++) {
                int row = warp_n + p * 16 + ((lane >> 4) << 3) + (lane & 7);
                int kbyte = kb + ((lane >> 3) & 1) * 16;
                uint32_t off = swz((uint32_t)(row * 128 + kbyte));
                LDM4(bh[2*p][0], bh[2*p][1], bh[2*p+1][0], bh[2*p+1][1], sBh + off);
                LDM4(bl[2*p][0], bl[2*p][1], bl[2*p+1][0], bl[2*p+1][1], sBl + off);
            }
#pragma unroll
            for (int mt = 0; mt < 2; mt++) {
                int row = warp_m + mt * 16 + (lane & 15);
                int kbyte = kb + (lane >> 4) * 16;
                uint32_t off = swz((uint32_t)(row * 128 + kbyte));
                uint32_t ah[4], al[4];
                LDM4(ah[0], ah[1], ah[2], ah[3], sAh + off);
                LDM4(al[0], al[1], al[2], al[3], sAl + off);
#pragma unroll
                for (int nt = 0; nt < 4; nt++) MMA_BF16(acc[mt][nt], ah, bh[nt]);
#pragma unroll
                for (int nt = 0; nt < 4; nt++) MMA_BF16(acc[mt][nt], ah, bl[nt]);
#pragma unroll
                for (int nt = 0; nt < 4; nt++) MMA_BF16(acc[mt][nt], al, bh[nt]);
            }
        }
    };

    // ---- 2-stage pipeline (occupancy-2 covers the single-chunk gap) ----
    const int NC = Ksplit >> 6;
    stage_load(0, 0);
    for (int c = 0; c < NC; c++) {
        CP_WAIT0();
        __syncthreads();
        if (c + 1 < NC) stage_load(c + 1, (c + 1) & 1);
        mma_chunk(c & 1);
    }

    // ---- epilogue ----
    const int qrow = lane >> 2;
    const int qcol = (lane & 3) * 2;
#pragma unroll
    for (int mt = 0; mt < 2; mt++) {
        int row0 = m0 + warp_m + mt * 16 + qrow;
        int row1 = row0 + 8;
#pragma unroll
        for (int nt = 0; nt < 4; nt++) {
            int gn = n0 + warp_n + nt * 8 + qcol;
            if (gn >= Nvalid) continue;
            float2 v0 = make_float2(acc[mt][nt][0], acc[mt][nt][1]);
            float2 v1 = make_float2(acc[mt][nt][2], acc[mt][nt][3]);
            if (mode == 1) {
                float b0 = bias[gn], b1 = bias[gn + 1];
                v0.x += b0; v0.y += b1; v1.x += b0; v1.y += b1;
                v0.x = (v0.x > 20.f) ? v0.x : log1pf(expf(v0.x));
                v0.y = (v0.y > 20.f) ? v0.y : log1pf(expf(v0.y));
                v1.x = (v1.x > 20.f) ? v1.x : log1pf(expf(v1.x));
                v1.y = (v1.y > 20.f) ? v1.y : log1pf(expf(v1.y));
            }
            if (mode == 2) {
                atomicAdd(&C[(size_t)row0 * ldc + gn],     v0.x);
                atomicAdd(&C[(size_t)row0 * ldc + gn + 1], v0.y);
                atomicAdd(&C[(size_t)row1 * ldc + gn],     v1.x);
                atomicAdd(&C[(size_t)row1 * ldc + gn + 1], v1.y);
            } else {
                *reinterpret_cast<float2*>(C + (size_t)row0 * ldc + gn) = v0;
                *reinterpret_cast<float2*>(C + (size_t)row1 * ldc + gn) = v1;
            }
        }
    }
}

// ---------------- fp32 -> bf16 hi/lo converters -------------------------------
__global__ void cvt_kernel(const float* __restrict__ src,
                           bf16* __restrict__ hi, bf16* __restrict__ lo, int n4)
{
    int i = blockIdx.x * blockDim.x + threadIdx.x;
    if (i >= n4) return;
    float4 v = reinterpret_cast<const float4*>(src)[i];
    bf16 h0, h1, h2, h3, l0, l1, l2, l3;
    split_bf16(v.x, h0, l0); split_bf16(v.y, h1, l1);
    split_bf16(v.z, h2, l2); split_bf16(v.w, h3, l3);
    uint32_t hA = ((uint32_t)__bfloat16_as_ushort(h1) << 16) | __bfloat16_as_ushort(h0);
    uint32_t hB = ((uint32_t)__bfloat16_as_ushort(h3) << 16) | __bfloat16_as_ushort(h2);
    uint32_t lA = ((uint32_t)__bfloat16_as_ushort(l1) << 16) | __bfloat16_as_ushort(l0);
    uint32_t lB = ((uint32_t)__bfloat16_as_ushort(l3) << 16) | __bfloat16_as_ushort(l2);
    reinterpret_cast<uint2*>(hi)[i] = make_uint2(hA, hB);
    reinterpret_cast<uint2*>(lo)[i] = make_uint2(lA, lB);
}

__global__ void cvt4_kernel(const float* s0, bf16* h0, bf16* l0, int n0,
                            const float* s1, bf16* h1, bf16* l1, int n1,
                            const float* s2, bf16* h2, bf16* l2, int n2,
                            const float* s3, bf16* h3, bf16* l3, int n3)
{
    int i = blockIdx.x * blockDim.x + threadIdx.x;
    const float* s; bf16 *h, *l; int j = i;
    if (j < n0)      { s = s0; h = h0; l = l0; }
    else { j -= n0;
    if (j < n1)      { s = s1; h = h1; l = l1; }
    else { j -= n1;
    if (j < n2)      { s = s2; h = h2; l = l2; }
    else { j -= n2;
    if (j < n3)      { s = s3; h = h3; l = l3; }
    else return; } } }
    float4 v = reinterpret_cast<const float4*>(s)[j];
    bf16 a0, a1, a2, a3, b0, b1, b2, b3;
    split_bf16(v.x, a0, b0); split_bf16(v.y, a1, b1);
    split_bf16(v.z, a2, b2); split_bf16(v.w, a3, b3);
    uint32_t hA = ((uint32_t)__bfloat16_as_ushort(a1) << 16) | __bfloat16_as_ushort(a0);
    uint32_t hB = ((uint32_t)__bfloat16_as_ushort(a3) << 16) | __bfloat16_as_ushort(a2);
    uint32_t lA = ((uint32_t)__bfloat16_as_ushort(b1) << 16) | __bfloat16_as_ushort(b0);
    uint32_t lB = ((uint32_t)__bfloat16_as_ushort(b3) << 16) | __bfloat16_as_ushort(b2);
    reinterpret_cast<uint2*>(h)[j] = make_uint2(hA, hB);
    reinterpret_cast<uint2*>(l)[j] = make_uint2(lA, lB);
}

__global__ void cvt_xdbl_kernel(const float* __restrict__ xdbl,
                                bf16* __restrict__ hi, bf16* __restrict__ lo)
{
    int i = blockIdx.x * blockDim.x + threadIdx.x;
    int r = i >> 6, c = i & 63;
    float v = xdbl[r * XDBL_W + c];
    bf16 h, l; split_bf16(v, h, l);
    hi[i] = h; lo[i] = l;
}

// ---------------- fused residual-add + LayerNorm ------------------------------
__global__ void resln_kernel(const float* __restrict__ hin,
                             float* __restrict__ res,
                             bf16* __restrict__ hn_hi, bf16* __restrict__ hn_lo,
                             const float* __restrict__ w,
                             const float* __restrict__ b,
                             int first)
{
    const int l   = blockIdx.x;
    const int tid = threadIdx.x;
    float v[4];
    float s = 0.f, sq = 0.f;
#pragma unroll
    for (int i = 0; i < 4; i++) {
        int c = tid + i * 256;
        float x = hin[l * DMODEL + c];
        if (!first) x += res[l * DMODEL + c];
        res[l * DMODEL + c] = x;
        v[i] = x;
        s  += x;
        sq += x * x;
    }
    __shared__ float shs[8], shq[8];
    const int lane = tid & 31, warp = tid >> 5;
#pragma unroll
    for (int o = 16; o > 0; o >>= 1) {
        s  += __shfl_xor_sync(0xffffffffu, s,  o);
        sq += __shfl_xor_sync(0xffffffffu, sq, o);
    }
    if (lane == 0) { shs[warp] = s; shq[warp] = sq; }
    __syncthreads();
    s = 0.f; sq = 0.f;
#pragma unroll
    for (int i = 0; i < 8; i++) { s += shs[i]; sq += shq[i]; }

    const float inv = 1.f / (float)DMODEL;
    const float mu  = s * inv;
    const float var = sq * inv - mu * mu;
    const float rstd = rsqrtf(var + 1e-5f);
#pragma unroll
    for (int i = 0; i < 4; i++) {
        int c = tid + i * 256;
        float o = (v[i] - mu) * rstd * w[c] + b[c];
        bf16 h, lo; split_bf16(o, h, lo);
        hn_hi[l * DMODEL + c] = h;
        hn_lo[l * DMODEL + c] = lo;
    }
}

// ---------------- conv + SiLU; zeroes xdbl for split-K atomics ---------------
__global__ void conv_silu_kernel(const float* __restrict__ xz,
                                 const float* __restrict__ cw,
                                 const float* __restrict__ cb,
                                 float* __restrict__ xconv,
                                 bf16* __restrict__ xc_hi,
                                 bf16* __restrict__ xc_lo,
                                 float* __restrict__ xdbl_zero)
{
    const int idx = blockIdx.x * blockDim.x + threadIdx.x;
    if (idx >= L_SEQ * DINNER) return;
    const int l = idx >> 11;
    const int d = idx & (DINNER - 1);

    float acc = cb[d];
    const float w0 = cw[d*4+0], w1 = cw[d*4+1], w2 = cw[d*4+2], w3 = cw[d*4+3];
    if (l >= 3) acc = fmaf(w0, xz[(size_t)(l-3) * (2*DINNER) + d], acc);
    if (l >= 2) acc = fmaf(w1, xz[(size_t)(l-2) * (2*DINNER) + d], acc);
    if (l >= 1) acc = fmaf(w2, xz[(size_t)(l-1) * (2*DINNER) + d], acc);
    acc = fmaf(w3, xz[(size_t)l * (2*DINNER) + d], acc);

    acc = acc / (1.f + expf(-acc));
    xconv[idx] = acc;
    bf16 h, lo; split_bf16(acc, h, lo);
    xc_hi[idx] = h;
    xc_lo[idx] = lo;

    if (idx < L_SEQ * XDBL_W) xdbl_zero[idx] = 0.f;
}

// ---------------- 32x32 tiled transpose: delta/xconv/z -> [d][t] -------------
__global__ void transpose3_kernel(const float* __restrict__ dsrc,
                                  const float* __restrict__ xsrc,
                                  const float* __restrict__ zsrc,
                                  float* __restrict__ dT,
                                  float* __restrict__ xT,
                                  float* __restrict__ zT)
{
    __shared__ float tile[32][33];
    const float* src; float* dst; int lds;
    if (blockIdx.z == 0)      { src = dsrc; dst = dT; lds = DINNER; }
    else if (blockIdx.z == 1) { src = xsrc; dst = xT; lds = DINNER; }
    else                      { src = zsrc; dst = zT; lds = 2 * DINNER; }
    const int c0 = blockIdx.x * 32;   // d
    const int r0 = blockIdx.y * 32;   // t
    const int x = threadIdx.x, y0 = threadIdx.y;
#pragma unroll
    for (int i = 0; i < 4; i++) {
        int y = y0 + i * 8;
        tile[y][x] = src[(size_t)(r0 + y) * lds + c0 + x];
    }
    __syncthreads();
#pragma unroll
    for (int i = 0; i < 4; i++) {
        int y = y0 + i * 8;
        dst[(size_t)(c0 + y) * L_SEQ + r0 + x] = tile[x][y];
    }
}

// ---------------- yT [d][t] fp32 -> y hi/lo [t][d] bf16 ----------------------
__global__ void ytr_kernel(const float* __restrict__ yT,
                           bf16* __restrict__ y_hi, bf16* __restrict__ y_lo)
{
    __shared__ float tile[32][33];
    const int c0 = blockIdx.x * 32;   // t
    const int r0 = blockIdx.y * 32;   // d
    const int x = threadIdx.x, y0 = threadIdx.y;
#pragma unroll
    for (int i = 0; i < 4; i++) {
        int y = y0 + i * 8;
        tile[y][x] = yT[(size_t)(r0 + y) * L_SEQ + c0 + x];
    }
    __syncthreads();
#pragma unroll
    for (int i = 0; i < 4; i++) {
        int y = y0 + i * 8;
        float v = tile[x][y];
        bf16 h, l; split_bf16(v, h, l);
        y_hi[(size_t)(c0 + y) * DINNER + r0 + x] = h;
        y_lo[(size_t)(c0 + y) * DINNER + r0 + x] = l;
    }
}

// =============================================================================
// Chunked parallel scan on transposed inputs.
// One CTA per channel d; delta/xconv rows staged in smem (coalesced load).
// 256 threads = 16 chunks x 16 states; two-phase scan; writes yT [d][t] fp32.
// =============================================================================
__global__ void __launch_bounds__(256)
scan_kernel(const float* __restrict__ deltaT,
            const float* __restrict__ xcT,
            const float* __restrict__ zT,
            const float* __restrict__ xdbl,
            const float* __restrict__ A_log,
            const float* __restrict__ Dvec,
            float* __restrict__ yT)
{
    const int d    = blockIdx.x;
    const int tid  = threadIdx.x;
    const int lane = tid & 31;
    const int wrp  = tid >> 5;
    const int j    = wrp * 2 + (lane >> 4);
    const int s    = lane & 15;
    const int t0   = j * 64;

    __shared__ float s_dl[L_SEQ];
    __shared__ float s_xv[L_SEQ];
    __shared__ float shP[16][16];
    __shared__ float shS[16][16];

    for (int i = tid; i < L_SEQ; i += 256) {
        s_dl[i] = deltaT[(size_t)d * L_SEQ + i];
        s_xv[i] = xcT[(size_t)d * L_SEQ + i];
    }
    __syncthreads();

    const float a2 = -expf(A_log[d * DSTATE + s]) * 1.4426950408889634f;

    // ---- phase 1 ----
    float P = 1.f, S = 0.f;
#pragma unroll 4
    for (int k = 0; k < 64; k++) {
        const int t = t0 + k;
        const float dl = s_dl[t];
        const float Bs = xdbl[t * XDBL_W + DTRANK + s];
        const float dA = exp2f(dl * a2);
        P *= dA;
        S = fmaf(dA, S, dl * s_xv[t] * Bs);
    }
    shP[j][s] = P;
    shS[j][s] = S;
    __syncthreads();

    // ---- combine ----
    if (tid < 16) {
        const int ss = tid;
        float run = shS[0][ss];
#pragma unroll
        for (int jj = 1; jj < 16; jj++) {
            run = fmaf(shP[jj][ss], run, shS[jj][ss]);
            shS[jj][ss] = run;
        }
    }
    __syncthreads();

    // ---- phase 2 ----
    float h = (j == 0) ? 0.f : shS[j - 1][s];
    const float Dd = Dvec[d];
#pragma unroll 4
    for (int k = 0; k < 64; k++) {
        const int t = t0 + k;
        const float dl = s_dl[t];
        const float xv = s_xv[t];
        const float Bs = xdbl[t * XDBL_W + DTRANK + s];
        const float Cs = xdbl[t * XDBL_W + DTRANK + DSTATE + s];
        const float dA = exp2f(dl * a2);
        h = fmaf(dA, h, dl * xv * Bs);

        float acc = h * Cs;
        acc += __shfl_xor_sync(0xffffffffu, acc, 1);
        acc += __shfl_xor_sync(0xffffffffu, acc, 2);
        acc += __shfl_xor_sync(0xffffffffu, acc, 4);
        acc += __shfl_xor_sync(0xffffffffu, acc, 8);

        if (s == 0) {
            const float zv = zT[(size_t)d * L_SEQ + t];
            float yv = acc + xv * Dd;
            yv *= zv / (1.f + expf(-zv));
            yT[(size_t)d * L_SEQ + t] = yv;
        }
    }
}

// ---------------- host orchestration ----------------------------------------
extern "C" void kernel_launch(void* const* d_in, const int* in_sizes, int n_in,
                              void* d_out, int out_size)
{
    const float* input   = (const float*)d_in[0];
    const float* input_w = (const float*)d_in[2];
    const float* norm_w  = (const float*)d_in[3];
    const float* norm_b  = (const float*)d_in[4];
    const float* ipw     = (const float*)d_in[5];
    const float* cw      = (const float*)d_in[6];
    const float* cb      = (const float*)d_in[7];
    const float* xpw     = (const float*)d_in[8];
    const float* dtw     = (const float*)d_in[9];
    const float* dtb     = (const float*)d_in[10];
    const float* A_log   = (const float*)d_in[11];
    const float* ssm_D   = (const float*)d_in[12];
    const float* opw     = (const float*)d_in[13];

    float *res, *h, *xz, *xconv, *xdbl, *delta, *deltaT, *xcT, *zT, *yT;
    cudaGetSymbolAddress((void**)&res,    g_res);
    cudaGetSymbolAddress((void**)&h,      g_h);
    cudaGetSymbolAddress((void**)&xz,     g_xz);
    cudaGetSymbolAddress((void**)&xconv,  g_xconv);
    cudaGetSymbolAddress((void**)&xdbl,   g_xdbl);
    cudaGetSymbolAddress((void**)&delta,  g_delta);
    cudaGetSymbolAddress((void**)&deltaT, g_deltaT);
    cudaGetSymbolAddress((void**)&xcT,    g_xcT);
    cudaGetSymbolAddress((void**)&zT,     g_zT);
    cudaGetSymbolAddress((void**)&yT,     g_yT);

    bf16 *in_hi, *in_lo, *inw_hi, *inw_lo, *ipw_hi, *ipw_lo, *xpw_hi, *xpw_lo;
    bf16 *dtw_hi, *dtw_lo, *opw_hi, *opw_lo, *hn_hi, *hn_lo, *xc_hi, *xc_lo;
    bf16 *xd_hi, *xd_lo, *y_hi, *y_lo;
    cudaGetSymbolAddress((void**)&in_hi,  c_in_hi);  cudaGetSymbolAddress((void**)&in_lo,  c_in_lo);
    cudaGetSymbolAddress((void**)&inw_hi, c_inw_hi); cudaGetSymbolAddress((void**)&inw_lo, c_inw_lo);
    cudaGetSymbolAddress((void**)&ipw_hi, c_ipw_hi); cudaGetSymbolAddress((void**)&ipw_lo, c_ipw_lo);
    cudaGetSymbolAddress((void**)&xpw_hi, c_xpw_hi); cudaGetSymbolAddress((void**)&xpw_lo, c_xpw_lo);
    cudaGetSymbolAddress((void**)&dtw_hi, c_dtw_hi); cudaGetSymbolAddress((void**)&dtw_lo, c_dtw_lo);
    cudaGetSymbolAddress((void**)&opw_hi, c_opw_hi); cudaGetSymbolAddress((void**)&opw_lo, c_opw_lo);
    cudaGetSymbolAddress((void**)&hn_hi,  c_hn_hi);  cudaGetSymbolAddress((void**)&hn_lo,  c_hn_lo);
    cudaGetSymbolAddress((void**)&xc_hi,  c_xc_hi);  cudaGetSymbolAddress((void**)&xc_lo,  c_xc_lo);
    cudaGetSymbolAddress((void**)&xd_hi,  c_xd_hi);  cudaGetSymbolAddress((void**)&xd_lo,  c_xd_lo);
    cudaGetSymbolAddress((void**)&y_hi,   c_y_hi);   cudaGetSymbolAddress((void**)&y_lo,   c_y_lo);

    cudaFuncSetAttribute(mma_gemm, cudaFuncAttributeMaxDynamicSharedMemorySize, G_SMEM);

    // conversions
    cvt_kernel<<<(NLAYERS*2*DINNER*DMODEL/4 + 255)/256, 256>>>(
        ipw, ipw_hi, ipw_lo, NLAYERS*2*DINNER*DMODEL/4);
    cvt_kernel<<<(NLAYERS*DMODEL*DINNER/4 + 255)/256, 256>>>(
        opw, opw_hi, opw_lo, NLAYERS*DMODEL*DINNER/4);
    cvt4_kernel<<<(589824 + 255)/256, 256>>>(
        input,   in_hi,  in_lo,  L_SEQ*INLEN/4,
        input_w, inw_hi, inw_lo, DMODEL*INLEN/4,
        xpw,     xpw_hi, xpw_lo, NLAYERS*XDBL_W*DINNER/4,
        dtw,     dtw_hi, dtw_lo, NLAYERS*DINNER*DTRANK/4);

    // h = input @ input_w^T
    mma_gemm<<<dim3(DMODEL/128, L_SEQ/64), 256, G_SMEM>>>(
        in_hi, in_lo, INLEN, inw_hi, inw_lo, INLEN, h, DMODEL,
        DMODEL, INLEN, nullptr, 0);

    for (int i = 0; i < NLAYERS; i++) {
        resln_kernel<<<L_SEQ, 256>>>(h, res, hn_hi, hn_lo,
                                     norm_w + i*DMODEL, norm_b + i*DMODEL, i == 0);

        // xz = hn @ in_proj_w^T   (512 CTAs)
        mma_gemm<<<dim3((2*DINNER)/128, L_SEQ/64), 256, G_SMEM>>>(
            hn_hi, hn_lo, DMODEL,
            ipw_hi + (size_t)i*2*DINNER*DMODEL, ipw_lo + (size_t)i*2*DINNER*DMODEL, DMODEL,
            xz, 2*DINNER, 2*DINNER, DMODEL, nullptr, 0);

        conv_silu_kernel<<<(L_SEQ*DINNER)/256, 256>>>(
            xz, cw + (size_t)i*DINNER*4, cb + i*DINNER, xconv, xc_hi, xc_lo, xdbl);

        // x_dbl = xconv @ x_proj_w^T   split-K=8 (128 CTAs), atomic
        mma_gemm<<<dim3(1, L_SEQ/64, 8), 256, G_SMEM>>>(
            xc_hi, xc_lo, DINNER,
            xpw_hi + (size_t)i*XDBL_W*DINNER, xpw_lo + (size_t)i*XDBL_W*DINNER, DINNER,
            xdbl, XDBL_W, XDBL_W, DINNER/8, nullptr, 2);

        cvt_xdbl_kernel<<<(L_SEQ*DTRANK)/256, 256>>>(xdbl, xd_hi, xd_lo);

        // delta = softplus(xd @ dt_proj_w^T + bias)   (256 CTAs)
        mma_gemm<<<dim3(DINNER/128, L_SEQ/64), 256, G_SMEM>>>(
            xd_hi, xd_lo, DTRANK,
            dtw_hi + (size_t)i*DINNER*DTRANK, dtw_lo + (size_t)i*DINNER*DTRANK, DTRANK,
            delta, DINNER, DINNER, DTRANK, dtb + i*DINNER, 1);

        // transpose delta/xconv/z -> [d][t]
        transpose3_kernel<<<dim3(DINNER/32, L_SEQ/32, 3), dim3(32, 8)>>>(
            delta, xconv, xz + DINNER, deltaT, xcT, zT);

        // chunked parallel scan (2048 CTAs) -> yT [d][t]
        scan_kernel<<<DINNER, 256>>>(deltaT, xcT, zT, xdbl,
                                     A_log + (size_t)i*DINNER*DSTATE,
                                     ssm_D + i*DINNER, yT);

        // yT -> y hi/lo [t][d]
        ytr_kernel<<<dim3(L_SEQ/32, DINNER/32), dim3(32, 8)>>>(yT, y_hi, y_lo);

        // h(next) = y @ out_proj_w^T   (128 CTAs)
        float* outp = (i == NLAYERS-1) ? (float*)d_out : h;
        mma_gemm<<<dim3(DMODEL/128, L_SEQ/64), 256, G_SMEM>>>(
            y_hi, y_lo, DINNER,
            opw_hi + (size_t)i*DMODEL*DINNER, opw_lo + (size_t)i*DMODEL*DINNER, DINNER,
            outp, DMODEL, DMODEL, DINNER, nullptr, 0);
    }
}